// round 13
// baseline (speedup 1.0000x reference)
#include <cuda_runtime.h>
#include <cstdint>

// SphConv3 fused pipeline v12: v11 (329.1us) + 2-warps-per-node gather.

#define N_MAX 26001
#define E_MAX 520001

__device__ float  g_x[(size_t)N_MAX * 64];
__device__ float  g_agg[(size_t)N_MAX * 576];    // holds V = tf32(x*agg)
__device__ float  g_node[(size_t)N_MAX * 384];   // tf32-rounded
__device__ float4 g_pack[(size_t)E_MAX * 3];
__device__ int    g_deg[N_MAX];
__device__ int    g_off[N_MAX + 1];
__device__ int    g_cur[N_MAX];
__device__ float  g_wn1r[384 * 256];
__device__ float  g_wn2r[256 * 256];
__device__ float  g_wur[3 * 64 * 128];

static __device__ __forceinline__ float4 f4fma(float s, float4 w, float4 acc) {
    acc.x = fmaf(s, w.x, acc.x); acc.y = fmaf(s, w.y, acc.y);
    acc.z = fmaf(s, w.z, acc.z); acc.w = fmaf(s, w.w, acc.w);
    return acc;
}
static __device__ __forceinline__ float tf32r(float x) {
    float r;
    asm("cvt.rna.tf32.f32 %0, %1;" : "=f"(r) : "f"(x));
    return r;
}
static __device__ __forceinline__ float4 tf32r4(float4 v) {
    v.x = tf32r(v.x); v.y = tf32r(v.y); v.z = tf32r(v.z); v.w = tf32r(v.w);
    return v;
}
static __device__ __forceinline__ void mma_tf32(float* c, const uint32_t* a,
                                                uint32_t b0, uint32_t b1) {
    asm volatile(
        "mma.sync.aligned.m16n8k8.row.col.f32.tf32.tf32.f32 "
        "{%0,%1,%2,%3}, {%4,%5,%6,%7}, {%8,%9}, {%0,%1,%2,%3};"
        : "+f"(c[0]), "+f"(c[1]), "+f"(c[2]), "+f"(c[3])
        : "r"(a[0]), "r"(a[1]), "r"(a[2]), "r"(a[3]), "r"(b0), "r"(b1));
}
static __device__ __forceinline__ void cp16(float* s, const float* g) {
    uint32_t sa = (uint32_t)__cvta_generic_to_shared(s);
    asm volatile("cp.async.ca.shared.global [%0], [%1], 16;" :: "r"(sa), "l"(g));
}
#define CP_COMMIT() asm volatile("cp.async.commit_group;" ::: "memory")
#define CP_WAIT0()  asm volatile("cp.async.wait_group 0;" ::: "memory")
#define CP_WAIT1()  asm volatile("cp.async.wait_group 1;" ::: "memory")

// ---------------------------------------------------------------------------
__global__ void k_prep(const float* __restrict__ Wn1, const float* __restrict__ Wn2,
                       const float* __restrict__ W0, const float* __restrict__ W1,
                       const float* __restrict__ Wh) {
    int i = blockIdx.x * 256 + threadIdx.x;
    if (i < 24576)      ((float4*)g_wn1r)[i] = tf32r4(__ldg((const float4*)Wn1 + i));
    else if (i < 40960) ((float4*)g_wn2r)[i - 24576] = tf32r4(__ldg((const float4*)Wn2 + (i - 24576)));
    else if (i < 43008) ((float4*)g_wur)[i - 40960] = tf32r4(__ldg((const float4*)W0 + (i - 40960)));
    else if (i < 45056) ((float4*)g_wur)[i - 40960] = tf32r4(__ldg((const float4*)W1 + (i - 43008)));
    else if (i < 47104) ((float4*)g_wur)[i - 40960] = tf32r4(__ldg((const float4*)Wh + (i - 45056)));
}

__global__ void k_zero_deg(int N) {
    int i = blockIdx.x * blockDim.x + threadIdx.x;
    if (i < N) g_deg[i] = 0;
}

// ---------------------------------------------------------------------------
__global__ void k_down(const float* __restrict__ x, const float* __restrict__ Wd,
                       const float* __restrict__ bd, int N) {
    __shared__ float sX[16 * 256];
    int t = threadIdx.x;
    int row0 = blockIdx.x * 16;
    const float4* x4 = (const float4*)x + (size_t)row0 * 64;
    int lim = (N - row0) * 64;
    for (int idx = t; idx < 1024; idx += 256)
        ((float4*)sX)[idx] = (idx < lim) ? x4[idx] : make_float4(0.f, 0.f, 0.f, 0.f);
    __syncthreads();
    int cg = t & 15, rl = t >> 4;
    int row = row0 + rl;
    if (row >= N) return;
    float4 acc = *(const float4*)(bd + cg * 4);
    const float* xr = sX + rl * 256;
#pragma unroll 8
    for (int k = 0; k < 256; k++) {
        float4 w = __ldg((const float4*)(Wd + k * 64) + cg);
        acc = f4fma(xr[k], w, acc);
    }
    *(float4*)(g_x + (size_t)row * 64 + cg * 4) = acc;
}

// ---------------------------------------------------------------------------
__global__ void k_hist(const int* __restrict__ iv, int E) {
    int e = blockIdx.x * blockDim.x + threadIdx.x;
    if (e < E) atomicAdd(&g_deg[iv[e]], 1);
}

__global__ void k_scan(int N) {
    extern __shared__ int si[];
    int* sDeg = si;
    int* sOff = si + N;
    __shared__ int warpTot[32];
    int t = threadIdx.x;
    for (int idx = t; idx < N; idx += 1024) sDeg[idx] = g_deg[idx];
    __syncthreads();
    int chunk = (N + 1023) >> 10;
    int base = t * chunk;
    int s = 0;
    for (int k = 0; k < chunk; k++) {
        int i = base + k;
        if (i < N) s += sDeg[i];
    }
    int lane = t & 31, w = t >> 5;
    int pre = s;
#pragma unroll
    for (int o = 1; o < 32; o <<= 1) {
        int u = __shfl_up_sync(0xffffffffu, pre, o);
        if (lane >= o) pre += u;
    }
    if (lane == 31) warpTot[w] = pre;
    __syncthreads();
    if (w == 0) {
        int v = warpTot[lane];
#pragma unroll
        for (int o = 1; o < 32; o <<= 1) {
            int u = __shfl_up_sync(0xffffffffu, v, o);
            if (lane >= o) v += u;
        }
        warpTot[lane] = v;
    }
    __syncthreads();
    int excl = pre - s + (w ? warpTot[w - 1] : 0);
    for (int k = 0; k < chunk; k++) {
        int i = base + k;
        if (i < N) { sOff[i] = excl; excl += sDeg[i]; }
    }
    __syncthreads();
    for (int idx = t; idx < N; idx += 1024) {
        int v = sOff[idx];
        g_off[idx] = v;
        g_cur[idx] = v;
    }
    if (t == 1023) g_off[N] = excl;
}

__global__ void k_scatter(const int* __restrict__ iv, const int* __restrict__ jv,
                          const float* __restrict__ factor,
                          const float* __restrict__ sph0, const float* __restrict__ sph1,
                          int E) {
    int e = blockIdx.x * blockDim.x + threadIdx.x;
    if (e >= E) return;
    int i = iv[e];
    int pos = atomicAdd(&g_cur[i], 1);
    float4 A, B, C;
    A.x = __int_as_float(jv[e]);
    A.y = __int_as_float(e);
    A.z = __ldg(factor + e);
    A.w = __ldg(sph1 + (size_t)e * 3 + 0);
    B.x = __ldg(sph1 + (size_t)e * 3 + 1);
    B.y = __ldg(sph1 + (size_t)e * 3 + 2);
    B.z = __ldg(sph0 + (size_t)e * 5 + 0);
    B.w = __ldg(sph0 + (size_t)e * 5 + 1);
    C.x = __ldg(sph0 + (size_t)e * 5 + 2);
    C.y = __ldg(sph0 + (size_t)e * 5 + 3);
    C.z = __ldg(sph0 + (size_t)e * 5 + 4);
    C.w = 0.f;
    g_pack[(size_t)pos * 3 + 0] = A;
    g_pack[(size_t)pos * 3 + 1] = B;
    g_pack[(size_t)pos * 3 + 2] = C;
}

// ---------------------------------------------------------------------------
// gather: TWO warps per node. sub-warp handles edges koff+sub, koff+sub+2, ...
// Partials combined via smem. 256 thr/block = 8 warps = 4 nodes/block.
__global__ void __launch_bounds__(256) k_gather(const float* __restrict__ rbf, int N) {
    __shared__ float sPart[4][9][64];   // [node-in-block][channel][col]
    int gw = (blockIdx.x * blockDim.x + threadIdx.x) >> 5;  // global warp
    int w = gw >> 1;                    // node
    int sub = gw & 1;
    int lane = threadIdx.x & 31;
    int nb = (threadIdx.x >> 6);        // node-in-block 0..3
    float2 acc[9];
#pragma unroll
    for (int c = 0; c < 9; c++) acc[c] = make_float2(0.f, 0.f);

    if (w < N) {
        int koff = g_off[w], kend = g_off[w + 1];
        int k = koff + sub;

        float4 A, B, C;
        float2 xj = make_float2(0.f, 0.f), rb = make_float2(0.f, 0.f);
        A = make_float4(0.f, 0.f, 0.f, 0.f); B = A; C = A;
        if (k < kend) {
            A = g_pack[(size_t)k * 3 + 0];
            B = g_pack[(size_t)k * 3 + 1];
            C = g_pack[(size_t)k * 3 + 2];
            int j = __float_as_int(A.x);
            int e = __float_as_int(A.y);
            xj = *(const float2*)(g_x + (size_t)j * 64 + lane * 2);
            rb = __ldg((const float2*)(rbf + (size_t)e * 64) + lane);
        }
        while (k < kend) {
            float4 An = make_float4(0.f, 0.f, 0.f, 0.f), Bn = An, Cn = An;
            float2 xjn = make_float2(0.f, 0.f), rbn = xjn;
            int kn = k + 2;
            if (kn < kend) {
                An = g_pack[(size_t)kn * 3 + 0];
                Bn = g_pack[(size_t)kn * 3 + 1];
                Cn = g_pack[(size_t)kn * 3 + 2];
                int jn = __float_as_int(An.x);
                int en = __float_as_int(An.y);
                xjn = *(const float2*)(g_x + (size_t)jn * 64 + lane * 2);
                rbn = __ldg((const float2*)(rbf + (size_t)en * 64) + lane);
            }
            float l0x = xj.x * rb.x * A.z;
            float l0y = xj.y * rb.y * A.z;
            acc[0].x += l0x;                      acc[0].y += l0y;
            acc[1].x = fmaf(A.w, l0x, acc[1].x);  acc[1].y = fmaf(A.w, l0y, acc[1].y);
            acc[2].x = fmaf(B.x, l0x, acc[2].x);  acc[2].y = fmaf(B.x, l0y, acc[2].y);
            acc[3].x = fmaf(B.y, l0x, acc[3].x);  acc[3].y = fmaf(B.y, l0y, acc[3].y);
            acc[4].x = fmaf(B.z, l0x, acc[4].x);  acc[4].y = fmaf(B.z, l0y, acc[4].y);
            acc[5].x = fmaf(B.w, l0x, acc[5].x);  acc[5].y = fmaf(B.w, l0y, acc[5].y);
            acc[6].x = fmaf(C.x, l0x, acc[6].x);  acc[6].y = fmaf(C.x, l0y, acc[6].y);
            acc[7].x = fmaf(C.y, l0x, acc[7].x);  acc[7].y = fmaf(C.y, l0y, acc[7].y);
            acc[8].x = fmaf(C.z, l0x, acc[8].x);  acc[8].y = fmaf(C.z, l0y, acc[8].y);
            A = An; B = Bn; C = Cn; xj = xjn; rb = rbn;
            k = kn;
        }
    }

    // sub 1 deposits partials to smem
    if (sub == 1) {
#pragma unroll
        for (int c = 0; c < 9; c++)
            *(float2*)(&sPart[nb][c][lane * 2]) = acc[c];
    }
    __syncthreads();
    if (sub == 0 && w < N) {
        float2 xv = *(const float2*)(g_x + (size_t)w * 64 + lane * 2);
        float* base = g_agg + (size_t)w * 576 + lane * 2;
#pragma unroll
        for (int c = 0; c < 9; c++) {
            float2 p = *(const float2*)(&sPart[nb][c][lane * 2]);
            float2 v;
            v.x = tf32r((acc[c].x + p.x) * xv.x);
            v.y = tf32r((acc[c].y + p.y) * xv.y);
            *(float2*)(base + c * 64) = v;
        }
    }
}

// ---------------------------------------------------------------------------
// k_up_mma: tf32 mma. 64 nodes/block, 256 thr (proven config).
#define SV_S 68
#define SU_S 136
__global__ void __launch_bounds__(256) k_up_mma(const float* __restrict__ b0, int N) {
    extern __shared__ float sm[];
    float* sW = sm;               // 64*136 = 8704
    float* sV[2] = { sm + 8704, sm + 8704 + 4352 };
    int t = threadIdx.x, lane = t & 31, wid = t >> 5;
    int wm = wid & 1, wn = wid >> 1;
    int qr = lane >> 2, qc = lane & 3;
    int m = blockIdx.y;
    int tile0 = blockIdx.x * 64;

    int chBase = (m == 0) ? 0 : (m == 1) ? 1 : 4;
    int nch    = (m == 0) ? 1 : (m == 1) ? 3 : 5;

    {
        const float* Wg = g_wur + m * 8192;
#pragma unroll
        for (int i = 0; i < 8; i++) {
            int idx = t + i * 256;
            int r = idx >> 5, c4 = (idx & 31) * 4;
            cp16(sW + r * SU_S + c4, Wg + r * 128 + c4);
        }
#pragma unroll
        for (int i = 0; i < 4; i++) {
            int idx = t + i * 256;
            int r = idx >> 4, c4 = (idx & 15) * 4;
            cp16(sV[0] + r * SV_S + c4,
                 g_agg + (size_t)(tile0 + r) * 576 + chBase * 64 + c4);
        }
        CP_COMMIT();
    }

    float facc[2][4][4];
#pragma unroll
    for (int mt = 0; mt < 2; mt++)
#pragma unroll
        for (int nt = 0; nt < 4; nt++)
#pragma unroll
            for (int q = 0; q < 4; q++) facc[mt][nt][q] = 0.f;

    for (int ch = 0; ch < nch; ch++) {
        if (ch + 1 < nch) {
#pragma unroll
            for (int i = 0; i < 4; i++) {
                int idx = t + i * 256;
                int r = idx >> 4, c4 = (idx & 15) * 4;
                cp16(sV[(ch + 1) & 1] + r * SV_S + c4,
                     g_agg + (size_t)(tile0 + r) * 576 + (chBase + ch + 1) * 64 + c4);
            }
            CP_COMMIT();
            CP_WAIT1();
        } else {
            CP_WAIT0();
        }
        __syncthreads();
        const float* V = sV[ch & 1];

        float acc[2][4][4];
#pragma unroll
        for (int mt = 0; mt < 2; mt++)
#pragma unroll
            for (int nt = 0; nt < 4; nt++)
#pragma unroll
                for (int q = 0; q < 4; q++) acc[mt][nt][q] = 0.f;

#pragma unroll
        for (int k8 = 0; k8 < 8; k8++) {
            int kb = k8 * 8;
            uint32_t a[2][4];
#pragma unroll
            for (int mt = 0; mt < 2; mt++) {
                const uint32_t* p = (const uint32_t*)V +
                    (wm * 32 + mt * 16 + qr) * SV_S + kb + qc;
                a[mt][0] = p[0]; a[mt][2] = p[4];
                a[mt][1] = p[8 * SV_S]; a[mt][3] = p[8 * SV_S + 4];
            }
#pragma unroll
            for (int nt = 0; nt < 4; nt++) {
                const uint32_t* p = (const uint32_t*)sW +
                    (kb + qc) * SU_S + wn * 32 + nt * 8 + qr;
                uint32_t b0v = p[0], b1v = p[4 * SU_S];
                mma_tf32(acc[0][nt], a[0], b0v, b1v);
                mma_tf32(acc[1][nt], a[1], b0v, b1v);
            }
        }
        if (m == 0) {
#pragma unroll
            for (int mt = 0; mt < 2; mt++)
#pragma unroll
                for (int nt = 0; nt < 4; nt++)
#pragma unroll
                    for (int q = 0; q < 4; q++) facc[mt][nt][q] = acc[mt][nt][q];
        } else {
#pragma unroll
            for (int mt = 0; mt < 2; mt++)
#pragma unroll
                for (int nt = 0; nt < 4; nt++)
#pragma unroll
                    for (int q = 0; q < 4; q++)
                        facc[mt][nt][q] = fmaf(acc[mt][nt][q], acc[mt][nt][q], facc[mt][nt][q]);
        }
        __syncthreads();
    }

#pragma unroll
    for (int mt = 0; mt < 2; mt++) {
#pragma unroll
        for (int half = 0; half < 2; half++) {
            int n = tile0 + wm * 32 + mt * 16 + qr + half * 8;
            if (n < N) {
#pragma unroll
                for (int nt = 0; nt < 4; nt++) {
                    int c = wn * 32 + nt * 8 + qc * 2;
                    float2 o;
                    o.x = facc[mt][nt][half * 2 + 0];
                    o.y = facc[mt][nt][half * 2 + 1];
                    if (m == 0) { o.x += __ldg(b0 + c); o.y += __ldg(b0 + c + 1); }
                    o.x = tf32r(o.x); o.y = tf32r(o.y);
                    *(float2*)(g_node + (size_t)n * 384 + m * 128 + c) = o;
                }
            }
        }
    }
}

// ---------------------------------------------------------------------------
// k_mlp_mma: tf32 mma. 64 rows/block, 8 warps 2m x 4n, warp tile 32x64.
#define SN_S 388
#define SW_S 264
__global__ void __launch_bounds__(256) k_mlp_mma(
    const float* __restrict__ bn1, const float* __restrict__ lng,
    const float* __restrict__ lnb, const float* __restrict__ bn2,
    const float* __restrict__ x, float* __restrict__ out, int N) {
    extern __shared__ float sm[];
    float* sN = sm;                         // 64*388 = 24832
    float* sWb[2] = { sm + 24832, sm + 24832 + 8448 };  // each 32*264 = 8448
    float* sH = sm;                         // alias sN
    int t = threadIdx.x, lane = t & 31, wid = t >> 5;
    int wm = wid & 1, wn = wid >> 1;
    int row0 = blockIdx.x * 64;
    int qr = lane >> 2, qc = lane & 3;

    {
#pragma unroll
        for (int i = 0; i < 24; i++) {
            int idx = t + i * 256;
            int r = idx / 96, c4 = (idx - r * 96) * 4;
            cp16(sN + r * SN_S + c4, g_node + (size_t)(row0 + r) * 384 + c4);
        }
#pragma unroll
        for (int i = 0; i < 8; i++) {
            int idx = t + i * 256;
            int r = idx >> 6, c4 = (idx & 63) * 4;
            cp16(sWb[0] + r * SW_S + c4, g_wn1r + (size_t)r * 256 + c4);
        }
        CP_COMMIT();
    }

    float acc[2][8][4];
#pragma unroll
    for (int mt = 0; mt < 2; mt++)
#pragma unroll
        for (int nt = 0; nt < 8; nt++)
#pragma unroll
            for (int q = 0; q < 4; q++) acc[mt][nt][q] = 0.f;

    for (int kc = 0; kc < 12; kc++) {
        if (kc + 1 < 12) {
#pragma unroll
            for (int i = 0; i < 8; i++) {
                int idx = t + i * 256;
                int r = idx >> 6, c4 = (idx & 63) * 4;
                cp16(sWb[(kc + 1) & 1] + r * SW_S + c4,
                     g_wn1r + (size_t)((kc + 1) * 32 + r) * 256 + c4);
            }
            CP_COMMIT();
            CP_WAIT1();
        } else {
            CP_WAIT0();
        }
        __syncthreads();
        const float* sW = sWb[kc & 1];
#pragma unroll
        for (int k8 = 0; k8 < 4; k8++) {
            int kb = kc * 32 + k8 * 8;
            uint32_t a[2][4];
#pragma unroll
            for (int mt = 0; mt < 2; mt++) {
                const uint32_t* p = (const uint32_t*)sN +
                    (wm * 32 + mt * 16 + qr) * SN_S + kb + qc;
                a[mt][0] = p[0]; a[mt][2] = p[4];
                a[mt][1] = p[8 * SN_S]; a[mt][3] = p[8 * SN_S + 4];
            }
#pragma unroll
            for (int nt = 0; nt < 8; nt++) {
                const uint32_t* p = (const uint32_t*)sW +
                    (k8 * 8 + qc) * SW_S + wn * 64 + nt * 8 + qr;
                uint32_t b0 = p[0], b1 = p[4 * SW_S];
                mma_tf32(acc[0][nt], a[0], b0, b1);
                mma_tf32(acc[1][nt], a[1], b0, b1);
            }
        }
        __syncthreads();
    }

#pragma unroll
    for (int mt = 0; mt < 2; mt++)
#pragma unroll
        for (int nt = 0; nt < 8; nt++) {
            int r = wm * 32 + mt * 16 + qr;
            int c = wn * 64 + nt * 8 + qc * 2;
            *(float2*)(sH + r * SN_S + c) = make_float2(acc[mt][nt][0], acc[mt][nt][1]);
            *(float2*)(sH + (r + 8) * SN_S + c) = make_float2(acc[mt][nt][2], acc[mt][nt][3]);
        }
    __syncthreads();

    {
        float pb[8], pg[8], pl[8];
#pragma unroll
        for (int k2 = 0; k2 < 8; k2++) {
            int col = lane + 32 * k2;
            pb[k2] = __ldg(bn1 + col);
            pg[k2] = __ldg(lng + col);
            pl[k2] = __ldg(lnb + col);
        }
#pragma unroll
        for (int rr = 0; rr < 8; rr++) {
            int r = wid * 8 + rr;
            float* hr = sH + r * SN_S;
            float vv[8];
            float s1 = 0.f, s2 = 0.f;
#pragma unroll
            for (int k2 = 0; k2 < 8; k2++) {
                float v = hr[lane + 32 * k2] + pb[k2];
                vv[k2] = v; s1 += v; s2 = fmaf(v, v, s2);
            }
#pragma unroll
            for (int o = 16; o > 0; o >>= 1) {
                s1 += __shfl_xor_sync(0xffffffffu, s1, o);
                s2 += __shfl_xor_sync(0xffffffffu, s2, o);
            }
            float mean = s1 * (1.f / 256.f);
            float var = s2 * (1.f / 256.f) - mean * mean;
            float rstd = rsqrtf(var + 1e-5f);
#pragma unroll
            for (int k2 = 0; k2 < 8; k2++) {
                float y = (vv[k2] - mean) * rstd * pg[k2] + pl[k2];
                hr[lane + 32 * k2] = tf32r(y / (1.f + __expf(-y)));
            }
        }
    }
    __syncthreads();

    {
#pragma unroll
        for (int i = 0; i < 8; i++) {
            int idx = t + i * 256;
            int r = idx >> 6, c4 = (idx & 63) * 4;
            cp16(sWb[0] + r * SW_S + c4, g_wn2r + (size_t)r * 256 + c4);
        }
        CP_COMMIT();
    }

#pragma unroll
    for (int mt = 0; mt < 2; mt++)
#pragma unroll
        for (int nt = 0; nt < 8; nt++)
#pragma unroll
            for (int q = 0; q < 4; q++) acc[mt][nt][q] = 0.f;

    for (int kc = 0; kc < 8; kc++) {
        if (kc + 1 < 8) {
#pragma unroll
            for (int i = 0; i < 8; i++) {
                int idx = t + i * 256;
                int r = idx >> 6, c4 = (idx & 63) * 4;
                cp16(sWb[(kc + 1) & 1] + r * SW_S + c4,
                     g_wn2r + (size_t)((kc + 1) * 32 + r) * 256 + c4);
            }
            CP_COMMIT();
            CP_WAIT1();
        } else {
            CP_WAIT0();
        }
        __syncthreads();
        const float* sW = sWb[kc & 1];
#pragma unroll
        for (int k8 = 0; k8 < 4; k8++) {
            int kb = kc * 32 + k8 * 8;
            uint32_t a[2][4];
#pragma unroll
            for (int mt = 0; mt < 2; mt++) {
                const uint32_t* p = (const uint32_t*)sH +
                    (wm * 32 + mt * 16 + qr) * SN_S + kb + qc;
                a[mt][0] = p[0]; a[mt][2] = p[4];
                a[mt][1] = p[8 * SN_S]; a[mt][3] = p[8 * SN_S + 4];
            }
#pragma unroll
            for (int nt = 0; nt < 8; nt++) {
                const uint32_t* p = (const uint32_t*)sW +
                    (k8 * 8 + qc) * SW_S + wn * 64 + nt * 8 + qr;
                uint32_t b0 = p[0], b1 = p[4 * SW_S];
                mma_tf32(acc[0][nt], a[0], b0, b1);
                mma_tf32(acc[1][nt], a[1], b0, b1);
            }
        }
        __syncthreads();
    }

#pragma unroll
    for (int mt = 0; mt < 2; mt++) {
        int rl = wm * 32 + mt * 16 + qr;
#pragma unroll
        for (int half = 0; half < 2; half++) {
            int rg = row0 + rl + half * 8;
            if (rg < N) {
#pragma unroll
                for (int nt = 0; nt < 8; nt++) {
                    int c = wn * 64 + nt * 8 + qc * 2;
                    float2 xv = __ldg((const float2*)(x + (size_t)rg * 256 + c));
                    float2 o;
                    o.x = acc[mt][nt][half * 2 + 0] + __ldg(bn2 + c) + xv.x;
                    o.y = acc[mt][nt][half * 2 + 1] + __ldg(bn2 + c + 1) + xv.y;
                    *(float2*)(out + (size_t)rg * 256 + c) = o;
                }
            }
        }
    }
}

// ---------------------------------------------------------------------------
extern "C" void kernel_launch(void* const* d_in, const int* in_sizes, int n_in,
                              void* d_out, int out_size) {
    const float* x      = (const float*)d_in[0];
    const float* rbf    = (const float*)d_in[1];
    const float* factor = (const float*)d_in[2];
    const float* sph0   = (const float*)d_in[3];
    const float* sph1   = (const float*)d_in[4];
    const float* Wd     = (const float*)d_in[5];
    const float* bd     = (const float*)d_in[6];
    const float* Wu0    = (const float*)d_in[7];
    const float* bu0    = (const float*)d_in[8];
    const float* Wu1    = (const float*)d_in[9];
    const float* Wuh    = (const float*)d_in[10];
    const float* Wn1    = (const float*)d_in[11];
    const float* bn1    = (const float*)d_in[12];
    const float* lng    = (const float*)d_in[13];
    const float* lnb    = (const float*)d_in[14];
    const float* Wn2    = (const float*)d_in[15];
    const float* bn2    = (const float*)d_in[16];
    const int*   jv     = (const int*)d_in[17];
    const int*   iv     = (const int*)d_in[18];
    float* out = (float*)d_out;

    int N = in_sizes[0] / 256;
    int E = in_sizes[17];

    int mlpSmem = (24832 + 2 * 8448) * 4;   // 167,680 B
    int upSmem  = (8704 + 2 * 4352) * 4;    // 69,632 B

    static bool inited = false;
    static cudaStream_t sideStream;
    static cudaEvent_t evFork, evJoin;
    if (!inited) {
        cudaStreamCreateWithFlags(&sideStream, cudaStreamNonBlocking);
        cudaEventCreateWithFlags(&evFork, cudaEventDisableTiming);
        cudaEventCreateWithFlags(&evJoin, cudaEventDisableTiming);
        cudaFuncSetAttribute(k_up_mma,  cudaFuncAttributeMaxDynamicSharedMemorySize, upSmem);
        cudaFuncSetAttribute(k_scan,    cudaFuncAttributeMaxDynamicSharedMemorySize, 2 * (N_MAX + 4) * 4);
        cudaFuncSetAttribute(k_mlp_mma, cudaFuncAttributeMaxDynamicSharedMemorySize, mlpSmem);
        inited = true;
    }

    cudaEventRecord(evFork, 0);
    cudaStreamWaitEvent(sideStream, evFork, 0);

    // side chain (B): zero_deg -> hist -> scan -> scatter
    k_zero_deg<<<(N + 255) / 256, 256, 0, sideStream>>>(N);
    k_hist<<<(E + 255) / 256, 256, 0, sideStream>>>(iv, E);
    k_scan<<<1, 1024, 2 * (N + 4) * 4, sideStream>>>(N);
    k_scatter<<<(E + 255) / 256, 256, 0, sideStream>>>(iv, jv, factor, sph0, sph1, E);

    // main chain (A): prep -> down
    k_prep<<<184, 256>>>(Wn1, Wn2, Wu0, Wu1, Wuh);
    k_down<<<(N + 15) / 16, 256>>>(x, Wd, bd, N);

    cudaEventRecord(evJoin, sideStream);
    cudaStreamWaitEvent(0, evJoin, 0);

    k_gather<<<(N * 2 + 7) / 8, 256>>>(rbf, N);
    dim3 upGrid((N + 63) / 64, 3);
    k_up_mma<<<upGrid, 256, upSmem>>>(bu0, N);
    k_mlp_mma<<<(N + 63) / 64, 256, mlpSmem>>>(bn1, lng, lnb, bn2, x, out, N);
}

// round 14
// speedup vs baseline: 1.1604x; 1.1604x over previous
#include <cuda_runtime.h>
#include <cuda_fp16.h>
#include <cstdint>

// SphConv3 fused pipeline v13: fp16 mma.sync m16n8k16 for k_up / k_mlp
// (legacy tf32 mma.sync underperforms on sm_103; fp16 doubles K per instr).
// Gather = v11 proven form, stream-fork overlap kept.

#define N_MAX 26001
#define E_MAX 520001

__device__ float   g_x[(size_t)N_MAX * 64];
__device__ __half2 g_aggh[(size_t)N_MAX * 288];   // V = half(x*agg) [N][9][32]
__device__ __half2 g_nodeh[(size_t)N_MAX * 192];  // node [N][384] as half2
__device__ float4  g_pack[(size_t)E_MAX * 3];
__device__ int     g_deg[N_MAX];
__device__ int     g_off[N_MAX + 1];
__device__ int     g_cur[N_MAX];
__device__ __half2 g_wn1h[192 * 256];             // Wn1 packed [k2][n]
__device__ __half2 g_wn2h[128 * 256];             // Wn2 packed [k2][n]
__device__ __half2 g_wuh[3 * 32 * 128];           // Wu  packed [m][k2][n]

static __device__ __forceinline__ float4 f4fma(float s, float4 w, float4 acc) {
    acc.x = fmaf(s, w.x, acc.x); acc.y = fmaf(s, w.y, acc.y);
    acc.z = fmaf(s, w.z, acc.z); acc.w = fmaf(s, w.w, acc.w);
    return acc;
}
static __device__ __forceinline__ void mma_f16(float* c, const uint32_t* a,
                                               uint32_t b0, uint32_t b1) {
    asm volatile(
        "mma.sync.aligned.m16n8k16.row.col.f32.f16.f16.f32 "
        "{%0,%1,%2,%3}, {%4,%5,%6,%7}, {%8,%9}, {%0,%1,%2,%3};"
        : "+f"(c[0]), "+f"(c[1]), "+f"(c[2]), "+f"(c[3])
        : "r"(a[0]), "r"(a[1]), "r"(a[2]), "r"(a[3]), "r"(b0), "r"(b1));
}
static __device__ __forceinline__ void cp16(void* s, const void* g) {
    uint32_t sa = (uint32_t)__cvta_generic_to_shared(s);
    asm volatile("cp.async.ca.shared.global [%0], [%1], 16;" :: "r"(sa), "l"(g));
}
#define CP_COMMIT() asm volatile("cp.async.commit_group;" ::: "memory")
#define CP_WAIT0()  asm volatile("cp.async.wait_group 0;" ::: "memory")
#define CP_WAIT1()  asm volatile("cp.async.wait_group 1;" ::: "memory")

// ---------------------------------------------------------------------------
// k_prep: pack all GEMM weights into k-pair half2 layout [k/2][n]
__global__ void k_prep(const float* __restrict__ Wn1, const float* __restrict__ Wn2,
                       const float* __restrict__ W0, const float* __restrict__ W1,
                       const float* __restrict__ Wh) {
    int i = blockIdx.x * 256 + threadIdx.x;
    if (i < 49152) {
        int k2 = i >> 8, n = i & 255;
        g_wn1h[i] = __floats2half2_rn(Wn1[(size_t)(2 * k2) * 256 + n],
                                      Wn1[(size_t)(2 * k2 + 1) * 256 + n]);
    } else if (i < 81920) {
        int j = i - 49152;
        int k2 = j >> 8, n = j & 255;
        g_wn2h[j] = __floats2half2_rn(Wn2[(size_t)(2 * k2) * 256 + n],
                                      Wn2[(size_t)(2 * k2 + 1) * 256 + n]);
    } else if (i < 94208) {
        int j = i - 81920;
        int m = j >> 12;
        int r = j & 4095;
        int k2 = r >> 7, n = r & 127;
        const float* W = (m == 0) ? W0 : (m == 1) ? W1 : Wh;
        g_wuh[j] = __floats2half2_rn(W[(size_t)(2 * k2) * 128 + n],
                                     W[(size_t)(2 * k2 + 1) * 128 + n]);
    }
}

__global__ void k_zero_deg(int N) {
    int i = blockIdx.x * blockDim.x + threadIdx.x;
    if (i < N) g_deg[i] = 0;
}

// ---------------------------------------------------------------------------
__global__ void k_down(const float* __restrict__ x, const float* __restrict__ Wd,
                       const float* __restrict__ bd, int N) {
    __shared__ float sX[16 * 256];
    int t = threadIdx.x;
    int row0 = blockIdx.x * 16;
    const float4* x4 = (const float4*)x + (size_t)row0 * 64;
    int lim = (N - row0) * 64;
    for (int idx = t; idx < 1024; idx += 256)
        ((float4*)sX)[idx] = (idx < lim) ? x4[idx] : make_float4(0.f, 0.f, 0.f, 0.f);
    __syncthreads();
    int cg = t & 15, rl = t >> 4;
    int row = row0 + rl;
    if (row >= N) return;
    float4 acc = *(const float4*)(bd + cg * 4);
    const float* xr = sX + rl * 256;
#pragma unroll 8
    for (int k = 0; k < 256; k++) {
        float4 w = __ldg((const float4*)(Wd + k * 64) + cg);
        acc = f4fma(xr[k], w, acc);
    }
    *(float4*)(g_x + (size_t)row * 64 + cg * 4) = acc;
}

// ---------------------------------------------------------------------------
__global__ void k_hist(const int* __restrict__ iv, int E) {
    int e = blockIdx.x * blockDim.x + threadIdx.x;
    if (e < E) atomicAdd(&g_deg[iv[e]], 1);
}

__global__ void k_scan(int N) {
    extern __shared__ int si[];
    int* sDeg = si;
    int* sOff = si + N;
    __shared__ int warpTot[32];
    int t = threadIdx.x;
    for (int idx = t; idx < N; idx += 1024) sDeg[idx] = g_deg[idx];
    __syncthreads();
    int chunk = (N + 1023) >> 10;
    int base = t * chunk;
    int s = 0;
    for (int k = 0; k < chunk; k++) {
        int i = base + k;
        if (i < N) s += sDeg[i];
    }
    int lane = t & 31, w = t >> 5;
    int pre = s;
#pragma unroll
    for (int o = 1; o < 32; o <<= 1) {
        int u = __shfl_up_sync(0xffffffffu, pre, o);
        if (lane >= o) pre += u;
    }
    if (lane == 31) warpTot[w] = pre;
    __syncthreads();
    if (w == 0) {
        int v = warpTot[lane];
#pragma unroll
        for (int o = 1; o < 32; o <<= 1) {
            int u = __shfl_up_sync(0xffffffffu, v, o);
            if (lane >= o) v += u;
        }
        warpTot[lane] = v;
    }
    __syncthreads();
    int excl = pre - s + (w ? warpTot[w - 1] : 0);
    for (int k = 0; k < chunk; k++) {
        int i = base + k;
        if (i < N) { sOff[i] = excl; excl += sDeg[i]; }
    }
    __syncthreads();
    for (int idx = t; idx < N; idx += 1024) {
        int v = sOff[idx];
        g_off[idx] = v;
        g_cur[idx] = v;
    }
    if (t == 1023) g_off[N] = excl;
}

__global__ void k_scatter(const int* __restrict__ iv, const int* __restrict__ jv,
                          const float* __restrict__ factor,
                          const float* __restrict__ sph0, const float* __restrict__ sph1,
                          int E) {
    int e = blockIdx.x * blockDim.x + threadIdx.x;
    if (e >= E) return;
    int i = iv[e];
    int pos = atomicAdd(&g_cur[i], 1);
    float4 A, B, C;
    A.x = __int_as_float(jv[e]);
    A.y = __int_as_float(e);
    A.z = __ldg(factor + e);
    A.w = __ldg(sph1 + (size_t)e * 3 + 0);
    B.x = __ldg(sph1 + (size_t)e * 3 + 1);
    B.y = __ldg(sph1 + (size_t)e * 3 + 2);
    B.z = __ldg(sph0 + (size_t)e * 5 + 0);
    B.w = __ldg(sph0 + (size_t)e * 5 + 1);
    C.x = __ldg(sph0 + (size_t)e * 5 + 2);
    C.y = __ldg(sph0 + (size_t)e * 5 + 3);
    C.z = __ldg(sph0 + (size_t)e * 5 + 4);
    C.w = 0.f;
    g_pack[(size_t)pos * 3 + 0] = A;
    g_pack[(size_t)pos * 3 + 1] = B;
    g_pack[(size_t)pos * 3 + 2] = C;
}

// ---------------------------------------------------------------------------
// gather: warp per node; depth-2 pipeline (v11 proven); emits half2 V
__global__ void __launch_bounds__(256) k_gather(const float* __restrict__ rbf, int N) {
    int w = (blockIdx.x * blockDim.x + threadIdx.x) >> 5;
    if (w >= N) return;
    int lane = threadIdx.x & 31;
    float2 acc[9];
#pragma unroll
    for (int c = 0; c < 9; c++) acc[c] = make_float2(0.f, 0.f);
    int k = g_off[w], kend = g_off[w + 1];

    float4 A, B, C;
    float2 xj = make_float2(0.f, 0.f), rb = make_float2(0.f, 0.f);
    A = make_float4(0.f, 0.f, 0.f, 0.f); B = A; C = A;
    if (k < kend) {
        A = g_pack[(size_t)k * 3 + 0];
        B = g_pack[(size_t)k * 3 + 1];
        C = g_pack[(size_t)k * 3 + 2];
        int j = __float_as_int(A.x);
        int e = __float_as_int(A.y);
        xj = *(const float2*)(g_x + (size_t)j * 64 + lane * 2);
        rb = __ldg((const float2*)(rbf + (size_t)e * 64) + lane);
    }
    while (k < kend) {
        float4 An = make_float4(0.f, 0.f, 0.f, 0.f), Bn = An, Cn = An;
        float2 xjn = make_float2(0.f, 0.f), rbn = xjn;
        int kn = k + 1;
        if (kn < kend) {
            An = g_pack[(size_t)kn * 3 + 0];
            Bn = g_pack[(size_t)kn * 3 + 1];
            Cn = g_pack[(size_t)kn * 3 + 2];
            int jn = __float_as_int(An.x);
            int en = __float_as_int(An.y);
            xjn = *(const float2*)(g_x + (size_t)jn * 64 + lane * 2);
            rbn = __ldg((const float2*)(rbf + (size_t)en * 64) + lane);
        }
        float l0x = xj.x * rb.x * A.z;
        float l0y = xj.y * rb.y * A.z;
        acc[0].x += l0x;                      acc[0].y += l0y;
        acc[1].x = fmaf(A.w, l0x, acc[1].x);  acc[1].y = fmaf(A.w, l0y, acc[1].y);
        acc[2].x = fmaf(B.x, l0x, acc[2].x);  acc[2].y = fmaf(B.x, l0y, acc[2].y);
        acc[3].x = fmaf(B.y, l0x, acc[3].x);  acc[3].y = fmaf(B.y, l0y, acc[3].y);
        acc[4].x = fmaf(B.z, l0x, acc[4].x);  acc[4].y = fmaf(B.z, l0y, acc[4].y);
        acc[5].x = fmaf(B.w, l0x, acc[5].x);  acc[5].y = fmaf(B.w, l0y, acc[5].y);
        acc[6].x = fmaf(C.x, l0x, acc[6].x);  acc[6].y = fmaf(C.x, l0y, acc[6].y);
        acc[7].x = fmaf(C.y, l0x, acc[7].x);  acc[7].y = fmaf(C.y, l0y, acc[7].y);
        acc[8].x = fmaf(C.z, l0x, acc[8].x);  acc[8].y = fmaf(C.z, l0y, acc[8].y);
        A = An; B = Bn; C = Cn; xj = xjn; rb = rbn;
        k = kn;
    }
    float2 xv = *(const float2*)(g_x + (size_t)w * 64 + lane * 2);
    __half2* base = g_aggh + (size_t)w * 288 + lane;
#pragma unroll
    for (int c = 0; c < 9; c++)
        base[c * 32] = __floats2half2_rn(acc[c].x * xv.x, acc[c].y * xv.y);
}

// ---------------------------------------------------------------------------
// k_up_mma fp16: 64 nodes/block, 256 thr, 8 warps 2m x 4n, warp tile 32x32.
// K=64 -> 4 k16 steps. V tiles double-buffered via cp.async.
#define SV2 36     // V stride in half2 (mod 32 == 4)
#define SU2 136    // W stride in half2 (mod 32 == 8)
__global__ void __launch_bounds__(256) k_up_mma(const float* __restrict__ b0, int N) {
    extern __shared__ __half2 smh[];
    __half2* sW = smh;                       // 32*136 = 4352 half2
    __half2* sV[2] = { smh + 4352, smh + 4352 + 2304 };  // each 64*36
    int t = threadIdx.x, lane = t & 31, wid = t >> 5;
    int wm = wid & 1, wn = wid >> 1;
    int qr = lane >> 2, qc = lane & 3;
    int m = blockIdx.y;
    int tile0 = blockIdx.x * 64;

    int chBase = (m == 0) ? 0 : (m == 1) ? 1 : 4;
    int nch    = (m == 0) ? 1 : (m == 1) ? 3 : 5;

    {
        const __half2* Wg = g_wuh + m * 4096;
#pragma unroll
        for (int i = 0; i < 4; i++) {
            int idx = t + i * 256;                 // 1024 f4 = 4096 half2
            int r = idx >> 5, c4 = (idx & 31) * 4;
            cp16(sW + r * SU2 + c4, Wg + r * 128 + c4);
        }
#pragma unroll
        for (int i = 0; i < 2; i++) {
            int idx = t + i * 256;                 // 512 f4 = 2048 half2
            int r = idx >> 3, c4 = (idx & 7) * 4;
            cp16(sV[0] + r * SV2 + c4,
                 g_aggh + (size_t)(tile0 + r) * 288 + chBase * 32 + c4);
        }
        CP_COMMIT();
    }

    float facc[2][4][4];
#pragma unroll
    for (int mt = 0; mt < 2; mt++)
#pragma unroll
        for (int nt = 0; nt < 4; nt++)
#pragma unroll
            for (int q = 0; q < 4; q++) facc[mt][nt][q] = 0.f;

    for (int ch = 0; ch < nch; ch++) {
        if (ch + 1 < nch) {
#pragma unroll
            for (int i = 0; i < 2; i++) {
                int idx = t + i * 256;
                int r = idx >> 3, c4 = (idx & 7) * 4;
                cp16(sV[(ch + 1) & 1] + r * SV2 + c4,
                     g_aggh + (size_t)(tile0 + r) * 288 + (chBase + ch + 1) * 32 + c4);
            }
            CP_COMMIT();
            CP_WAIT1();
        } else {
            CP_WAIT0();
        }
        __syncthreads();
        const __half2* V = sV[ch & 1];

        float acc[2][4][4];
#pragma unroll
        for (int mt = 0; mt < 2; mt++)
#pragma unroll
            for (int nt = 0; nt < 4; nt++)
#pragma unroll
                for (int q = 0; q < 4; q++) acc[mt][nt][q] = 0.f;

#pragma unroll
        for (int ks = 0; ks < 4; ks++) {
            int k2b = ks * 8;
            uint32_t a[2][4];
#pragma unroll
            for (int mt = 0; mt < 2; mt++) {
                const uint32_t* p = (const uint32_t*)V +
                    (wm * 32 + mt * 16 + qr) * SV2 + k2b + qc;
                a[mt][0] = p[0]; a[mt][2] = p[4];
                a[mt][1] = p[8 * SV2]; a[mt][3] = p[8 * SV2 + 4];
            }
#pragma unroll
            for (int nt = 0; nt < 4; nt++) {
                const uint32_t* pb = (const uint32_t*)sW +
                    (k2b + qc) * SU2 + wn * 32 + nt * 8 + qr;
                uint32_t b0v = pb[0], b1v = pb[4 * SU2];
                mma_f16(acc[0][nt], a[0], b0v, b1v);
                mma_f16(acc[1][nt], a[1], b0v, b1v);
            }
        }
        if (m == 0) {
#pragma unroll
            for (int mt = 0; mt < 2; mt++)
#pragma unroll
                for (int nt = 0; nt < 4; nt++)
#pragma unroll
                    for (int q = 0; q < 4; q++) facc[mt][nt][q] = acc[mt][nt][q];
        } else {
#pragma unroll
            for (int mt = 0; mt < 2; mt++)
#pragma unroll
                for (int nt = 0; nt < 4; nt++)
#pragma unroll
                    for (int q = 0; q < 4; q++)
                        facc[mt][nt][q] = fmaf(acc[mt][nt][q], acc[mt][nt][q], facc[mt][nt][q]);
        }
        __syncthreads();
    }

#pragma unroll
    for (int mt = 0; mt < 2; mt++) {
#pragma unroll
        for (int half = 0; half < 2; half++) {
            int n = tile0 + wm * 32 + mt * 16 + qr + half * 8;
            if (n < N) {
#pragma unroll
                for (int nt = 0; nt < 4; nt++) {
                    int c = wn * 32 + nt * 8 + qc * 2;
                    float ox = facc[mt][nt][half * 2 + 0];
                    float oy = facc[mt][nt][half * 2 + 1];
                    if (m == 0) { ox += __ldg(b0 + c); oy += __ldg(b0 + c + 1); }
                    g_nodeh[(size_t)n * 192 + m * 64 + wn * 16 + nt * 4 + qc] =
                        __floats2half2_rn(ox, oy);
                }
            }
        }
    }
}

// ---------------------------------------------------------------------------
// k_mlp_mma fp16: 64 rows/block, 8 warps 2m x 4n, warp tile 32x64.
// GEMM1 K=384 (12 chunks of k32), LN fp32, GEMM2 K=256 (8 chunks).
#define SA2 196    // A stride half2 (mod 32 == 4)
#define SB2 264    // W stride half2 (mod 32 == 8)
#define SC_S 260   // fp32 spill stride
__global__ void __launch_bounds__(256) k_mlp_mma(
    const float* __restrict__ bn1, const float* __restrict__ lng,
    const float* __restrict__ lnb, const float* __restrict__ bn2,
    const float* __restrict__ x, float* __restrict__ out, int N) {
    extern __shared__ char smc[];
    __half2* sA = (__half2*)smc;                        // 64*196*4 = 50176 B
    float*   sC = (float*)(smc + 50176);                // 64*260*4 = 66560 B
    __half2* sWb[2] = { (__half2*)(smc + 116736),
                        (__half2*)(smc + 116736 + 16896) };  // each 16*264*4
    int t = threadIdx.x, lane = t & 31, wid = t >> 5;
    int wm = wid & 1, wn = wid >> 1;
    int row0 = blockIdx.x * 64;
    int qr = lane >> 2, qc = lane & 3;

    {
#pragma unroll
        for (int i = 0; i < 12; i++) {
            int idx = t + i * 256;                  // 3072 f4: 64 rows x 48 f4
            int r = idx / 48, c4 = (idx - r * 48) * 4;
            cp16(sA + r * SA2 + c4, g_nodeh + (size_t)(row0 + r) * 192 + c4);
        }
#pragma unroll
        for (int i = 0; i < 4; i++) {
            int idx = t + i * 256;                  // 1024 f4: 16 rows x 64 f4
            int r = idx >> 6, c4 = (idx & 63) * 4;
            cp16(sWb[0] + r * SB2 + c4, g_wn1h + (size_t)r * 256 + c4);
        }
        CP_COMMIT();
    }

    float acc[2][8][4];
#pragma unroll
    for (int mt = 0; mt < 2; mt++)
#pragma unroll
        for (int nt = 0; nt < 8; nt++)
#pragma unroll
            for (int q = 0; q < 4; q++) acc[mt][nt][q] = 0.f;

    // GEMM1: 12 chunks of k=32 (k2=16)
    for (int kc = 0; kc < 12; kc++) {
        if (kc + 1 < 12) {
#pragma unroll
            for (int i = 0; i < 4; i++) {
                int idx = t + i * 256;
                int r = idx >> 6, c4 = (idx & 63) * 4;
                cp16(sWb[(kc + 1) & 1] + r * SB2 + c4,
                     g_wn1h + (size_t)((kc + 1) * 16 + r) * 256 + c4);
            }
            CP_COMMIT();
            CP_WAIT1();
        } else {
            CP_WAIT0();
        }
        __syncthreads();
        const __half2* sW = sWb[kc & 1];
#pragma unroll
        for (int ks = 0; ks < 2; ks++) {
            int k2b = kc * 16 + ks * 8;
            uint32_t a[2][4];
#pragma unroll
            for (int mt = 0; mt < 2; mt++) {
                const uint32_t* p = (const uint32_t*)sA +
                    (wm * 32 + mt * 16 + qr) * SA2 + k2b + qc;
                a[mt][0] = p[0]; a[mt][2] = p[4];
                a[mt][1] = p[8 * SA2]; a[mt][3] = p[8 * SA2 + 4];
            }
#pragma unroll
            for (int nt = 0; nt < 8; nt++) {
                const uint32_t* pb = (const uint32_t*)sW +
                    (ks * 8 + qc) * SB2 + wn * 64 + nt * 8 + qr;
                uint32_t b0 = pb[0], b1 = pb[4 * SB2];
                mma_f16(acc[0][nt], a[0], b0, b1);
                mma_f16(acc[1][nt], a[1], b0, b1);
            }
        }
        __syncthreads();
    }

    // spill fp32 C1
#pragma unroll
    for (int mt = 0; mt < 2; mt++)
#pragma unroll
        for (int nt = 0; nt < 8; nt++) {
            int r = wm * 32 + mt * 16 + qr;
            int c = wn * 64 + nt * 8 + qc * 2;
            *(float2*)(sC + r * SC_S + c) = make_float2(acc[mt][nt][0], acc[mt][nt][1]);
            *(float2*)(sC + (r + 8) * SC_S + c) = make_float2(acc[mt][nt][2], acc[mt][nt][3]);
        }
    __syncthreads();

    // LN + SiLU (fp32, in sC), hoisted params
    {
        float pb[8], pg[8], pl[8];
#pragma unroll
        for (int k2 = 0; k2 < 8; k2++) {
            int col = lane + 32 * k2;
            pb[k2] = __ldg(bn1 + col);
            pg[k2] = __ldg(lng + col);
            pl[k2] = __ldg(lnb + col);
        }
#pragma unroll
        for (int rr = 0; rr < 8; rr++) {
            int r = wid * 8 + rr;
            float* hr = sC + r * SC_S;
            float vv[8];
            float s1 = 0.f, s2 = 0.f;
#pragma unroll
            for (int k2 = 0; k2 < 8; k2++) {
                float v = hr[lane + 32 * k2] + pb[k2];
                vv[k2] = v; s1 += v; s2 = fmaf(v, v, s2);
            }
#pragma unroll
            for (int o = 16; o > 0; o >>= 1) {
                s1 += __shfl_xor_sync(0xffffffffu, s1, o);
                s2 += __shfl_xor_sync(0xffffffffu, s2, o);
            }
            float mean = s1 * (1.f / 256.f);
            float var = s2 * (1.f / 256.f) - mean * mean;
            float rstd = rsqrtf(var + 1e-5f);
#pragma unroll
            for (int k2 = 0; k2 < 8; k2++) {
                float y = (vv[k2] - mean) * rstd * pg[k2] + pl[k2];
                hr[lane + 32 * k2] = y / (1.f + __expf(-y));
            }
        }
    }
    __syncthreads();

    // preload W2 chunk 0; convert H (fp32 sC) -> half2 into sA
    {
#pragma unroll
        for (int i = 0; i < 4; i++) {
            int idx = t + i * 256;
            int r = idx >> 6, c4 = (idx & 63) * 4;
            cp16(sWb[0] + r * SB2 + c4, g_wn2h + (size_t)r * 256 + c4);
        }
        CP_COMMIT();
#pragma unroll
        for (int i = 0; i < 32; i++) {
            int idx = t + i * 256;                  // 8192: 64 rows x 128 half2
            int r = idx >> 7, c2 = idx & 127;
            sA[r * SA2 + c2] = __floats2half2_rn(sC[r * SC_S + 2 * c2],
                                                 sC[r * SC_S + 2 * c2 + 1]);
        }
    }
    __syncthreads();

    // GEMM2: 8 chunks of k=32
#pragma unroll
    for (int mt = 0; mt < 2; mt++)
#pragma unroll
        for (int nt = 0; nt < 8; nt++)
#pragma unroll
            for (int q = 0; q < 4; q++) acc[mt][nt][q] = 0.f;

    for (int kc = 0; kc < 8; kc++) {
        if (kc + 1 < 8) {
#pragma unroll
            for (int i = 0; i < 4; i++) {
                int idx = t + i * 256;
                int r = idx >> 6, c4 = (idx & 63) * 4;
                cp16(sWb[(kc + 1) & 1] + r * SB2 + c4,
                     g_wn2h + (size_t)((kc + 1) * 16 + r) * 256 + c4);
            }
            CP_COMMIT();
            CP_WAIT1();
        } else {
            CP_WAIT0();
        }
        __syncthreads();
        const __half2* sW = sWb[kc & 1];
#pragma unroll
        for (int ks = 0; ks < 2; ks++) {
            int k2b = kc * 16 + ks * 8;
            uint32_t a[2][4];
#pragma unroll
            for (int mt = 0; mt < 2; mt++) {
                const uint32_t* p = (const uint32_t*)sA +
                    (wm * 32 + mt * 16 + qr) * SA2 + k2b + qc;
                a[mt][0] = p[0]; a[mt][2] = p[4];
                a[mt][1] = p[8 * SA2]; a[mt][3] = p[8 * SA2 + 4];
            }
#pragma unroll
            for (int nt = 0; nt < 8; nt++) {
                const uint32_t* pb = (const uint32_t*)sW +
                    (ks * 8 + qc) * SB2 + wn * 64 + nt * 8 + qr;
                uint32_t b0 = pb[0], b1 = pb[4 * SB2];
                mma_f16(acc[0][nt], a[0], b0, b1);
                mma_f16(acc[1][nt], a[1], b0, b1);
            }
        }
        __syncthreads();
    }

    // epilogue: + bn2 + x -> out
#pragma unroll
    for (int mt = 0; mt < 2; mt++) {
        int rl = wm * 32 + mt * 16 + qr;
#pragma unroll
        for (int half = 0; half < 2; half++) {
            int rg = row0 + rl + half * 8;
            if (rg < N) {
#pragma unroll
                for (int nt = 0; nt < 8; nt++) {
                    int c = wn * 64 + nt * 8 + qc * 2;
                    float2 xv = __ldg((const float2*)(x + (size_t)rg * 256 + c));
                    float2 o;
                    o.x = acc[mt][nt][half * 2 + 0] + __ldg(bn2 + c) + xv.x;
                    o.y = acc[mt][nt][half * 2 + 1] + __ldg(bn2 + c + 1) + xv.y;
                    *(float2*)(out + (size_t)rg * 256 + c) = o;
                }
            }
        }
    }
}

// ---------------------------------------------------------------------------
extern "C" void kernel_launch(void* const* d_in, const int* in_sizes, int n_in,
                              void* d_out, int out_size) {
    const float* x      = (const float*)d_in[0];
    const float* rbf    = (const float*)d_in[1];
    const float* factor = (const float*)d_in[2];
    const float* sph0   = (const float*)d_in[3];
    const float* sph1   = (const float*)d_in[4];
    const float* Wd     = (const float*)d_in[5];
    const float* bd     = (const float*)d_in[6];
    const float* Wu0    = (const float*)d_in[7];
    const float* bu0    = (const float*)d_in[8];
    const float* Wu1    = (const float*)d_in[9];
    const float* Wuh    = (const float*)d_in[10];
    const float* Wn1    = (const float*)d_in[11];
    const float* bn1    = (const float*)d_in[12];
    const float* lng    = (const float*)d_in[13];
    const float* lnb    = (const float*)d_in[14];
    const float* Wn2    = (const float*)d_in[15];
    const float* bn2    = (const float*)d_in[16];
    const int*   jv     = (const int*)d_in[17];
    const int*   iv     = (const int*)d_in[18];
    float* out = (float*)d_out;

    int N = in_sizes[0] / 256;
    int E = in_sizes[17];

    int mlpSmem = 116736 + 2 * 16896;   // 150,528 B
    int upSmem  = (4352 + 2 * 2304) * 4; // 35,840 B

    static bool inited = false;
    static cudaStream_t sideStream;
    static cudaEvent_t evFork, evJoin;
    if (!inited) {
        cudaStreamCreateWithFlags(&sideStream, cudaStreamNonBlocking);
        cudaEventCreateWithFlags(&evFork, cudaEventDisableTiming);
        cudaEventCreateWithFlags(&evJoin, cudaEventDisableTiming);
        cudaFuncSetAttribute(k_up_mma,  cudaFuncAttributeMaxDynamicSharedMemorySize, upSmem);
        cudaFuncSetAttribute(k_scan,    cudaFuncAttributeMaxDynamicSharedMemorySize, 2 * (N_MAX + 4) * 4);
        cudaFuncSetAttribute(k_mlp_mma, cudaFuncAttributeMaxDynamicSharedMemorySize, mlpSmem);
        inited = true;
    }

    cudaEventRecord(evFork, 0);
    cudaStreamWaitEvent(sideStream, evFork, 0);

    // side chain (B): zero_deg -> hist -> scan -> scatter
    k_zero_deg<<<(N + 255) / 256, 256, 0, sideStream>>>(N);
    k_hist<<<(E + 255) / 256, 256, 0, sideStream>>>(iv, E);
    k_scan<<<1, 1024, 2 * (N + 4) * 4, sideStream>>>(N);
    k_scatter<<<(E + 255) / 256, 256, 0, sideStream>>>(iv, jv, factor, sph0, sph1, E);

    // main chain (A): prep -> down
    k_prep<<<368, 256>>>(Wn1, Wn2, Wu0, Wu1, Wuh);
    k_down<<<(N + 15) / 16, 256>>>(x, Wd, bd, N);

    cudaEventRecord(evJoin, sideStream);
    cudaStreamWaitEvent(0, evJoin, 0);

    k_gather<<<(N + 7) / 8, 256>>>(rbf, N);
    dim3 upGrid((N + 63) / 64, 3);
    k_up_mma<<<upGrid, 256, upSmem>>>(bu0, N);
    k_mlp_mma<<<(N + 63) / 64, 256, mlpSmem>>>(bn1, lng, lnb, bn2, x, out, N);
}

// round 15
// speedup vs baseline: 1.1611x; 1.0006x over previous
#include <cuda_runtime.h>
#include <cuda_fp16.h>
#include <cstdint>

// SphConv3 fused pipeline v14: v13 (287.6us) with zero_deg merged into prep and
// fork moved after prep -> launch order puts k_gather at profile index 5.

#define N_MAX 26001
#define E_MAX 520001

__device__ float   g_x[(size_t)N_MAX * 64];
__device__ __half2 g_aggh[(size_t)N_MAX * 288];   // V = half(x*agg) [N][9][32]
__device__ __half2 g_nodeh[(size_t)N_MAX * 192];  // node [N][384] as half2
__device__ float4  g_pack[(size_t)E_MAX * 3];
__device__ int     g_deg[N_MAX];
__device__ int     g_off[N_MAX + 1];
__device__ int     g_cur[N_MAX];
__device__ __half2 g_wn1h[192 * 256];             // Wn1 packed [k2][n]
__device__ __half2 g_wn2h[128 * 256];             // Wn2 packed [k2][n]
__device__ __half2 g_wuh[3 * 32 * 128];           // Wu  packed [m][k2][n]

static __device__ __forceinline__ float4 f4fma(float s, float4 w, float4 acc) {
    acc.x = fmaf(s, w.x, acc.x); acc.y = fmaf(s, w.y, acc.y);
    acc.z = fmaf(s, w.z, acc.z); acc.w = fmaf(s, w.w, acc.w);
    return acc;
}
static __device__ __forceinline__ void mma_f16(float* c, const uint32_t* a,
                                               uint32_t b0, uint32_t b1) {
    asm volatile(
        "mma.sync.aligned.m16n8k16.row.col.f32.f16.f16.f32 "
        "{%0,%1,%2,%3}, {%4,%5,%6,%7}, {%8,%9}, {%0,%1,%2,%3};"
        : "+f"(c[0]), "+f"(c[1]), "+f"(c[2]), "+f"(c[3])
        : "r"(a[0]), "r"(a[1]), "r"(a[2]), "r"(a[3]), "r"(b0), "r"(b1));
}
static __device__ __forceinline__ void cp16(void* s, const void* g) {
    uint32_t sa = (uint32_t)__cvta_generic_to_shared(s);
    asm volatile("cp.async.ca.shared.global [%0], [%1], 16;" :: "r"(sa), "l"(g));
}
#define CP_COMMIT() asm volatile("cp.async.commit_group;" ::: "memory")
#define CP_WAIT0()  asm volatile("cp.async.wait_group 0;" ::: "memory")
#define CP_WAIT1()  asm volatile("cp.async.wait_group 1;" ::: "memory")

// ---------------------------------------------------------------------------
// k_prep: pack weights to half2 [k/2][n] + zero g_deg
__global__ void k_prep(const float* __restrict__ Wn1, const float* __restrict__ Wn2,
                       const float* __restrict__ W0, const float* __restrict__ W1,
                       const float* __restrict__ Wh, int N) {
    int i = blockIdx.x * 256 + threadIdx.x;
    if (i < 49152) {
        int k2 = i >> 8, n = i & 255;
        g_wn1h[i] = __floats2half2_rn(Wn1[(size_t)(2 * k2) * 256 + n],
                                      Wn1[(size_t)(2 * k2 + 1) * 256 + n]);
    } else if (i < 81920) {
        int j = i - 49152;
        int k2 = j >> 8, n = j & 255;
        g_wn2h[j] = __floats2half2_rn(Wn2[(size_t)(2 * k2) * 256 + n],
                                      Wn2[(size_t)(2 * k2 + 1) * 256 + n]);
    } else if (i < 94208) {
        int j = i - 81920;
        int m = j >> 12;
        int r = j & 4095;
        int k2 = r >> 7, n = r & 127;
        const float* W = (m == 0) ? W0 : (m == 1) ? W1 : Wh;
        g_wuh[j] = __floats2half2_rn(W[(size_t)(2 * k2) * 128 + n],
                                     W[(size_t)(2 * k2 + 1) * 128 + n]);
    }
    if (i < N) g_deg[i] = 0;
}

// ---------------------------------------------------------------------------
__global__ void k_down(const float* __restrict__ x, const float* __restrict__ Wd,
                       const float* __restrict__ bd, int N) {
    __shared__ float sX[16 * 256];
    int t = threadIdx.x;
    int row0 = blockIdx.x * 16;
    const float4* x4 = (const float4*)x + (size_t)row0 * 64;
    int lim = (N - row0) * 64;
    for (int idx = t; idx < 1024; idx += 256)
        ((float4*)sX)[idx] = (idx < lim) ? x4[idx] : make_float4(0.f, 0.f, 0.f, 0.f);
    __syncthreads();
    int cg = t & 15, rl = t >> 4;
    int row = row0 + rl;
    if (row >= N) return;
    float4 acc = *(const float4*)(bd + cg * 4);
    const float* xr = sX + rl * 256;
#pragma unroll 8
    for (int k = 0; k < 256; k++) {
        float4 w = __ldg((const float4*)(Wd + k * 64) + cg);
        acc = f4fma(xr[k], w, acc);
    }
    *(float4*)(g_x + (size_t)row * 64 + cg * 4) = acc;
}

// ---------------------------------------------------------------------------
__global__ void k_hist(const int* __restrict__ iv, int E) {
    int e = blockIdx.x * blockDim.x + threadIdx.x;
    if (e < E) atomicAdd(&g_deg[iv[e]], 1);
}

__global__ void k_scan(int N) {
    extern __shared__ int si[];
    int* sDeg = si;
    int* sOff = si + N;
    __shared__ int warpTot[32];
    int t = threadIdx.x;
    for (int idx = t; idx < N; idx += 1024) sDeg[idx] = g_deg[idx];
    __syncthreads();
    int chunk = (N + 1023) >> 10;
    int base = t * chunk;
    int s = 0;
    for (int k = 0; k < chunk; k++) {
        int i = base + k;
        if (i < N) s += sDeg[i];
    }
    int lane = t & 31, w = t >> 5;
    int pre = s;
#pragma unroll
    for (int o = 1; o < 32; o <<= 1) {
        int u = __shfl_up_sync(0xffffffffu, pre, o);
        if (lane >= o) pre += u;
    }
    if (lane == 31) warpTot[w] = pre;
    __syncthreads();
    if (w == 0) {
        int v = warpTot[lane];
#pragma unroll
        for (int o = 1; o < 32; o <<= 1) {
            int u = __shfl_up_sync(0xffffffffu, v, o);
            if (lane >= o) v += u;
        }
        warpTot[lane] = v;
    }
    __syncthreads();
    int excl = pre - s + (w ? warpTot[w - 1] : 0);
    for (int k = 0; k < chunk; k++) {
        int i = base + k;
        if (i < N) { sOff[i] = excl; excl += sDeg[i]; }
    }
    __syncthreads();
    for (int idx = t; idx < N; idx += 1024) {
        int v = sOff[idx];
        g_off[idx] = v;
        g_cur[idx] = v;
    }
    if (t == 1023) g_off[N] = excl;
}

__global__ void k_scatter(const int* __restrict__ iv, const int* __restrict__ jv,
                          const float* __restrict__ factor,
                          const float* __restrict__ sph0, const float* __restrict__ sph1,
                          int E) {
    int e = blockIdx.x * blockDim.x + threadIdx.x;
    if (e >= E) return;
    int i = iv[e];
    int pos = atomicAdd(&g_cur[i], 1);
    float4 A, B, C;
    A.x = __int_as_float(jv[e]);
    A.y = __int_as_float(e);
    A.z = __ldg(factor + e);
    A.w = __ldg(sph1 + (size_t)e * 3 + 0);
    B.x = __ldg(sph1 + (size_t)e * 3 + 1);
    B.y = __ldg(sph1 + (size_t)e * 3 + 2);
    B.z = __ldg(sph0 + (size_t)e * 5 + 0);
    B.w = __ldg(sph0 + (size_t)e * 5 + 1);
    C.x = __ldg(sph0 + (size_t)e * 5 + 2);
    C.y = __ldg(sph0 + (size_t)e * 5 + 3);
    C.z = __ldg(sph0 + (size_t)e * 5 + 4);
    C.w = 0.f;
    g_pack[(size_t)pos * 3 + 0] = A;
    g_pack[(size_t)pos * 3 + 1] = B;
    g_pack[(size_t)pos * 3 + 2] = C;
}

// ---------------------------------------------------------------------------
// gather: warp per node; depth-2 pipeline; emits half2 V
__global__ void __launch_bounds__(256) k_gather(const float* __restrict__ rbf, int N) {
    int w = (blockIdx.x * blockDim.x + threadIdx.x) >> 5;
    if (w >= N) return;
    int lane = threadIdx.x & 31;
    float2 acc[9];
#pragma unroll
    for (int c = 0; c < 9; c++) acc[c] = make_float2(0.f, 0.f);
    int k = g_off[w], kend = g_off[w + 1];

    float4 A, B, C;
    float2 xj = make_float2(0.f, 0.f), rb = make_float2(0.f, 0.f);
    A = make_float4(0.f, 0.f, 0.f, 0.f); B = A; C = A;
    if (k < kend) {
        A = g_pack[(size_t)k * 3 + 0];
        B = g_pack[(size_t)k * 3 + 1];
        C = g_pack[(size_t)k * 3 + 2];
        int j = __float_as_int(A.x);
        int e = __float_as_int(A.y);
        xj = *(const float2*)(g_x + (size_t)j * 64 + lane * 2);
        rb = __ldg((const float2*)(rbf + (size_t)e * 64) + lane);
    }
    while (k < kend) {
        float4 An = make_float4(0.f, 0.f, 0.f, 0.f), Bn = An, Cn = An;
        float2 xjn = make_float2(0.f, 0.f), rbn = xjn;
        int kn = k + 1;
        if (kn < kend) {
            An = g_pack[(size_t)kn * 3 + 0];
            Bn = g_pack[(size_t)kn * 3 + 1];
            Cn = g_pack[(size_t)kn * 3 + 2];
            int jn = __float_as_int(An.x);
            int en = __float_as_int(An.y);
            xjn = *(const float2*)(g_x + (size_t)jn * 64 + lane * 2);
            rbn = __ldg((const float2*)(rbf + (size_t)en * 64) + lane);
        }
        float l0x = xj.x * rb.x * A.z;
        float l0y = xj.y * rb.y * A.z;
        acc[0].x += l0x;                      acc[0].y += l0y;
        acc[1].x = fmaf(A.w, l0x, acc[1].x);  acc[1].y = fmaf(A.w, l0y, acc[1].y);
        acc[2].x = fmaf(B.x, l0x, acc[2].x);  acc[2].y = fmaf(B.x, l0y, acc[2].y);
        acc[3].x = fmaf(B.y, l0x, acc[3].x);  acc[3].y = fmaf(B.y, l0y, acc[3].y);
        acc[4].x = fmaf(B.z, l0x, acc[4].x);  acc[4].y = fmaf(B.z, l0y, acc[4].y);
        acc[5].x = fmaf(B.w, l0x, acc[5].x);  acc[5].y = fmaf(B.w, l0y, acc[5].y);
        acc[6].x = fmaf(C.x, l0x, acc[6].x);  acc[6].y = fmaf(C.x, l0y, acc[6].y);
        acc[7].x = fmaf(C.y, l0x, acc[7].x);  acc[7].y = fmaf(C.y, l0y, acc[7].y);
        acc[8].x = fmaf(C.z, l0x, acc[8].x);  acc[8].y = fmaf(C.z, l0y, acc[8].y);
        A = An; B = Bn; C = Cn; xj = xjn; rb = rbn;
        k = kn;
    }
    float2 xv = *(const float2*)(g_x + (size_t)w * 64 + lane * 2);
    __half2* base = g_aggh + (size_t)w * 288 + lane;
#pragma unroll
    for (int c = 0; c < 9; c++)
        base[c * 32] = __floats2half2_rn(acc[c].x * xv.x, acc[c].y * xv.y);
}

// ---------------------------------------------------------------------------
// k_up_mma fp16: 64 nodes/block, 256 thr, 8 warps 2m x 4n, warp tile 32x32.
#define SV2 36
#define SU2 136
__global__ void __launch_bounds__(256) k_up_mma(const float* __restrict__ b0, int N) {
    extern __shared__ __half2 smh[];
    __half2* sW = smh;
    __half2* sV[2] = { smh + 4352, smh + 4352 + 2304 };
    int t = threadIdx.x, lane = t & 31, wid = t >> 5;
    int wm = wid & 1, wn = wid >> 1;
    int qr = lane >> 2, qc = lane & 3;
    int m = blockIdx.y;
    int tile0 = blockIdx.x * 64;

    int chBase = (m == 0) ? 0 : (m == 1) ? 1 : 4;
    int nch    = (m == 0) ? 1 : (m == 1) ? 3 : 5;

    {
        const __half2* Wg = g_wuh + m * 4096;
#pragma unroll
        for (int i = 0; i < 4; i++) {
            int idx = t + i * 256;
            int r = idx >> 5, c4 = (idx & 31) * 4;
            cp16(sW + r * SU2 + c4, Wg + r * 128 + c4);
        }
#pragma unroll
        for (int i = 0; i < 2; i++) {
            int idx = t + i * 256;
            int r = idx >> 3, c4 = (idx & 7) * 4;
            cp16(sV[0] + r * SV2 + c4,
                 g_aggh + (size_t)(tile0 + r) * 288 + chBase * 32 + c4);
        }
        CP_COMMIT();
    }

    float facc[2][4][4];
#pragma unroll
    for (int mt = 0; mt < 2; mt++)
#pragma unroll
        for (int nt = 0; nt < 4; nt++)
#pragma unroll
            for (int q = 0; q < 4; q++) facc[mt][nt][q] = 0.f;

    for (int ch = 0; ch < nch; ch++) {
        if (ch + 1 < nch) {
#pragma unroll
            for (int i = 0; i < 2; i++) {
                int idx = t + i * 256;
                int r = idx >> 3, c4 = (idx & 7) * 4;
                cp16(sV[(ch + 1) & 1] + r * SV2 + c4,
                     g_aggh + (size_t)(tile0 + r) * 288 + (chBase + ch + 1) * 32 + c4);
            }
            CP_COMMIT();
            CP_WAIT1();
        } else {
            CP_WAIT0();
        }
        __syncthreads();
        const __half2* V = sV[ch & 1];

        float acc[2][4][4];
#pragma unroll
        for (int mt = 0; mt < 2; mt++)
#pragma unroll
            for (int nt = 0; nt < 4; nt++)
#pragma unroll
                for (int q = 0; q < 4; q++) acc[mt][nt][q] = 0.f;

#pragma unroll
        for (int ks = 0; ks < 4; ks++) {
            int k2b = ks * 8;
            uint32_t a[2][4];
#pragma unroll
            for (int mt = 0; mt < 2; mt++) {
                const uint32_t* p = (const uint32_t*)V +
                    (wm * 32 + mt * 16 + qr) * SV2 + k2b + qc;
                a[mt][0] = p[0]; a[mt][2] = p[4];
                a[mt][1] = p[8 * SV2]; a[mt][3] = p[8 * SV2 + 4];
            }
#pragma unroll
            for (int nt = 0; nt < 4; nt++) {
                const uint32_t* pb = (const uint32_t*)sW +
                    (k2b + qc) * SU2 + wn * 32 + nt * 8 + qr;
                uint32_t b0v = pb[0], b1v = pb[4 * SU2];
                mma_f16(acc[0][nt], a[0], b0v, b1v);
                mma_f16(acc[1][nt], a[1], b0v, b1v);
            }
        }
        if (m == 0) {
#pragma unroll
            for (int mt = 0; mt < 2; mt++)
#pragma unroll
                for (int nt = 0; nt < 4; nt++)
#pragma unroll
                    for (int q = 0; q < 4; q++) facc[mt][nt][q] = acc[mt][nt][q];
        } else {
#pragma unroll
            for (int mt = 0; mt < 2; mt++)
#pragma unroll
                for (int nt = 0; nt < 4; nt++)
#pragma unroll
                    for (int q = 0; q < 4; q++)
                        facc[mt][nt][q] = fmaf(acc[mt][nt][q], acc[mt][nt][q], facc[mt][nt][q]);
        }
        __syncthreads();
    }

#pragma unroll
    for (int mt = 0; mt < 2; mt++) {
#pragma unroll
        for (int half = 0; half < 2; half++) {
            int n = tile0 + wm * 32 + mt * 16 + qr + half * 8;
            if (n < N) {
#pragma unroll
                for (int nt = 0; nt < 4; nt++) {
                    int c = wn * 32 + nt * 8 + qc * 2;
                    float ox = facc[mt][nt][half * 2 + 0];
                    float oy = facc[mt][nt][half * 2 + 1];
                    if (m == 0) { ox += __ldg(b0 + c); oy += __ldg(b0 + c + 1); }
                    g_nodeh[(size_t)n * 192 + m * 64 + wn * 16 + nt * 4 + qc] =
                        __floats2half2_rn(ox, oy);
                }
            }
        }
    }
}

// ---------------------------------------------------------------------------
// k_mlp_mma fp16: 64 rows/block, 8 warps 2m x 4n, warp tile 32x64.
#define SA2 196
#define SB2 264
#define SC_S 260
__global__ void __launch_bounds__(256) k_mlp_mma(
    const float* __restrict__ bn1, const float* __restrict__ lng,
    const float* __restrict__ lnb, const float* __restrict__ bn2,
    const float* __restrict__ x, float* __restrict__ out, int N) {
    extern __shared__ char smc[];
    __half2* sA = (__half2*)smc;
    float*   sC = (float*)(smc + 50176);
    __half2* sWb[2] = { (__half2*)(smc + 116736),
                        (__half2*)(smc + 116736 + 16896) };
    int t = threadIdx.x, lane = t & 31, wid = t >> 5;
    int wm = wid & 1, wn = wid >> 1;
    int row0 = blockIdx.x * 64;
    int qr = lane >> 2, qc = lane & 3;

    {
#pragma unroll
        for (int i = 0; i < 12; i++) {
            int idx = t + i * 256;
            int r = idx / 48, c4 = (idx - r * 48) * 4;
            cp16(sA + r * SA2 + c4, g_nodeh + (size_t)(row0 + r) * 192 + c4);
        }
#pragma unroll
        for (int i = 0; i < 4; i++) {
            int idx = t + i * 256;
            int r = idx >> 6, c4 = (idx & 63) * 4;
            cp16(sWb[0] + r * SB2 + c4, g_wn1h + (size_t)r * 256 + c4);
        }
        CP_COMMIT();
    }

    float acc[2][8][4];
#pragma unroll
    for (int mt = 0; mt < 2; mt++)
#pragma unroll
        for (int nt = 0; nt < 8; nt++)
#pragma unroll
            for (int q = 0; q < 4; q++) acc[mt][nt][q] = 0.f;

    for (int kc = 0; kc < 12; kc++) {
        if (kc + 1 < 12) {
#pragma unroll
            for (int i = 0; i < 4; i++) {
                int idx = t + i * 256;
                int r = idx >> 6, c4 = (idx & 63) * 4;
                cp16(sWb[(kc + 1) & 1] + r * SB2 + c4,
                     g_wn1h + (size_t)((kc + 1) * 16 + r) * 256 + c4);
            }
            CP_COMMIT();
            CP_WAIT1();
        } else {
            CP_WAIT0();
        }
        __syncthreads();
        const __half2* sW = sWb[kc & 1];
#pragma unroll
        for (int ks = 0; ks < 2; ks++) {
            int k2b = kc * 16 + ks * 8;
            uint32_t a[2][4];
#pragma unroll
            for (int mt = 0; mt < 2; mt++) {
                const uint32_t* p = (const uint32_t*)sA +
                    (wm * 32 + mt * 16 + qr) * SA2 + k2b + qc;
                a[mt][0] = p[0]; a[mt][2] = p[4];
                a[mt][1] = p[8 * SA2]; a[mt][3] = p[8 * SA2 + 4];
            }
#pragma unroll
            for (int nt = 0; nt < 8; nt++) {
                const uint32_t* pb = (const uint32_t*)sW +
                    (ks * 8 + qc) * SB2 + wn * 64 + nt * 8 + qr;
                uint32_t b0 = pb[0], b1 = pb[4 * SB2];
                mma_f16(acc[0][nt], a[0], b0, b1);
                mma_f16(acc[1][nt], a[1], b0, b1);
            }
        }
        __syncthreads();
    }

#pragma unroll
    for (int mt = 0; mt < 2; mt++)
#pragma unroll
        for (int nt = 0; nt < 8; nt++) {
            int r = wm * 32 + mt * 16 + qr;
            int c = wn * 64 + nt * 8 + qc * 2;
            *(float2*)(sC + r * SC_S + c) = make_float2(acc[mt][nt][0], acc[mt][nt][1]);
            *(float2*)(sC + (r + 8) * SC_S + c) = make_float2(acc[mt][nt][2], acc[mt][nt][3]);
        }
    __syncthreads();

    {
        float pb[8], pg[8], pl[8];
#pragma unroll
        for (int k2 = 0; k2 < 8; k2++) {
            int col = lane + 32 * k2;
            pb[k2] = __ldg(bn1 + col);
            pg[k2] = __ldg(lng + col);
            pl[k2] = __ldg(lnb + col);
        }
#pragma unroll
        for (int rr = 0; rr < 8; rr++) {
            int r = wid * 8 + rr;
            float* hr = sC + r * SC_S;
            float vv[8];
            float s1 = 0.f, s2 = 0.f;
#pragma unroll
            for (int k2 = 0; k2 < 8; k2++) {
                float v = hr[lane + 32 * k2] + pb[k2];
                vv[k2] = v; s1 += v; s2 = fmaf(v, v, s2);
            }
#pragma unroll
            for (int o = 16; o > 0; o >>= 1) {
                s1 += __shfl_xor_sync(0xffffffffu, s1, o);
                s2 += __shfl_xor_sync(0xffffffffu, s2, o);
            }
            float mean = s1 * (1.f / 256.f);
            float var = s2 * (1.f / 256.f) - mean * mean;
            float rstd = rsqrtf(var + 1e-5f);
#pragma unroll
            for (int k2 = 0; k2 < 8; k2++) {
                float y = (vv[k2] - mean) * rstd * pg[k2] + pl[k2];
                hr[lane + 32 * k2] = y / (1.f + __expf(-y));
            }
        }
    }
    __syncthreads();

    {
#pragma unroll
        for (int i = 0; i < 4; i++) {
            int idx = t + i * 256;
            int r = idx >> 6, c4 = (idx & 63) * 4;
            cp16(sWb[0] + r * SB2 + c4, g_wn2h + (size_t)r * 256 + c4);
        }
        CP_COMMIT();
#pragma unroll
        for (int i = 0; i < 32; i++) {
            int idx = t + i * 256;
            int r = idx >> 7, c2 = idx & 127;
            sA[r * SA2 + c2] = __floats2half2_rn(sC[r * SC_S + 2 * c2],
                                                 sC[r * SC_S + 2 * c2 + 1]);
        }
    }
    __syncthreads();

#pragma unroll
    for (int mt = 0; mt < 2; mt++)
#pragma unroll
        for (int nt = 0; nt < 8; nt++)
#pragma unroll
            for (int q = 0; q < 4; q++) acc[mt][nt][q] = 0.f;

    for (int kc = 0; kc < 8; kc++) {
        if (kc + 1 < 8) {
#pragma unroll
            for (int i = 0; i < 4; i++) {
                int idx = t + i * 256;
                int r = idx >> 6, c4 = (idx & 63) * 4;
                cp16(sWb[(kc + 1) & 1] + r * SB2 + c4,
                     g_wn2h + (size_t)((kc + 1) * 16 + r) * 256 + c4);
            }
            CP_COMMIT();
            CP_WAIT1();
        } else {
            CP_WAIT0();
        }
        __syncthreads();
        const __half2* sW = sWb[kc & 1];
#pragma unroll
        for (int ks = 0; ks < 2; ks++) {
            int k2b = kc * 16 + ks * 8;
            uint32_t a[2][4];
#pragma unroll
            for (int mt = 0; mt < 2; mt++) {
                const uint32_t* p = (const uint32_t*)sA +
                    (wm * 32 + mt * 16 + qr) * SA2 + k2b + qc;
                a[mt][0] = p[0]; a[mt][2] = p[4];
                a[mt][1] = p[8 * SA2]; a[mt][3] = p[8 * SA2 + 4];
            }
#pragma unroll
            for (int nt = 0; nt < 8; nt++) {
                const uint32_t* pb = (const uint32_t*)sW +
                    (ks * 8 + qc) * SB2 + wn * 64 + nt * 8 + qr;
                uint32_t b0 = pb[0], b1 = pb[4 * SB2];
                mma_f16(acc[0][nt], a[0], b0, b1);
                mma_f16(acc[1][nt], a[1], b0, b1);
            }
        }
        __syncthreads();
    }

#pragma unroll
    for (int mt = 0; mt < 2; mt++) {
        int rl = wm * 32 + mt * 16 + qr;
#pragma unroll
        for (int half = 0; half < 2; half++) {
            int rg = row0 + rl + half * 8;
            if (rg < N) {
#pragma unroll
                for (int nt = 0; nt < 8; nt++) {
                    int c = wn * 64 + nt * 8 + qc * 2;
                    float2 xv = __ldg((const float2*)(x + (size_t)rg * 256 + c));
                    float2 o;
                    o.x = acc[mt][nt][half * 2 + 0] + __ldg(bn2 + c) + xv.x;
                    o.y = acc[mt][nt][half * 2 + 1] + __ldg(bn2 + c + 1) + xv.y;
                    *(float2*)(out + (size_t)rg * 256 + c) = o;
                }
            }
        }
    }
}

// ---------------------------------------------------------------------------
extern "C" void kernel_launch(void* const* d_in, const int* in_sizes, int n_in,
                              void* d_out, int out_size) {
    const float* x      = (const float*)d_in[0];
    const float* rbf    = (const float*)d_in[1];
    const float* factor = (const float*)d_in[2];
    const float* sph0   = (const float*)d_in[3];
    const float* sph1   = (const float*)d_in[4];
    const float* Wd     = (const float*)d_in[5];
    const float* bd     = (const float*)d_in[6];
    const float* Wu0    = (const float*)d_in[7];
    const float* bu0    = (const float*)d_in[8];
    const float* Wu1    = (const float*)d_in[9];
    const float* Wuh    = (const float*)d_in[10];
    const float* Wn1    = (const float*)d_in[11];
    const float* bn1    = (const float*)d_in[12];
    const float* lng    = (const float*)d_in[13];
    const float* lnb    = (const float*)d_in[14];
    const float* Wn2    = (const float*)d_in[15];
    const float* bn2    = (const float*)d_in[16];
    const int*   jv     = (const int*)d_in[17];
    const int*   iv     = (const int*)d_in[18];
    float* out = (float*)d_out;

    int N = in_sizes[0] / 256;
    int E = in_sizes[17];

    int mlpSmem = 116736 + 2 * 16896;    // 150,528 B
    int upSmem  = (4352 + 2 * 2304) * 4; // 35,840 B

    static bool inited = false;
    static cudaStream_t sideStream;
    static cudaEvent_t evFork, evJoin;
    if (!inited) {
        cudaStreamCreateWithFlags(&sideStream, cudaStreamNonBlocking);
        cudaEventCreateWithFlags(&evFork, cudaEventDisableTiming);
        cudaEventCreateWithFlags(&evJoin, cudaEventDisableTiming);
        cudaFuncSetAttribute(k_up_mma,  cudaFuncAttributeMaxDynamicSharedMemorySize, upSmem);
        cudaFuncSetAttribute(k_scan,    cudaFuncAttributeMaxDynamicSharedMemorySize, 2 * (N_MAX + 4) * 4);
        cudaFuncSetAttribute(k_mlp_mma, cudaFuncAttributeMaxDynamicSharedMemorySize, mlpSmem);
        inited = true;
    }

    // launch 0: prep (weights pack + deg zero) on main stream
    k_prep<<<368, 256>>>(Wn1, Wn2, Wu0, Wu1, Wuh, N);

    // fork after prep: side chain builds CSR; main chain runs k_down
    cudaEventRecord(evFork, 0);
    cudaStreamWaitEvent(sideStream, evFork, 0);

    k_hist<<<(E + 255) / 256, 256, 0, sideStream>>>(iv, E);          // launch 1
    k_scan<<<1, 1024, 2 * (N + 4) * 4, sideStream>>>(N);             // launch 2
    k_scatter<<<(E + 255) / 256, 256, 0, sideStream>>>(iv, jv, factor, sph0, sph1, E); // 3

    k_down<<<(N + 15) / 16, 256>>>(x, Wd, bd, N);                    // launch 4

    cudaEventRecord(evJoin, sideStream);
    cudaStreamWaitEvent(0, evJoin, 0);

    k_gather<<<(N + 7) / 8, 256>>>(rbf, N);                          // launch 5 (profiled)
    dim3 upGrid((N + 63) / 64, 3);
    k_up_mma<<<upGrid, 256, upSmem>>>(bu0, N);
    k_mlp_mma<<<(N + 63) / 64, 256, mlpSmem>>>(bn1, lng, lnb, bn2, x, out, N);
}

// round 16
// speedup vs baseline: 1.2049x; 1.0378x over previous
#include <cuda_runtime.h>
#include <cuda_fp16.h>
#include <cstdint>

// SphConv3 fused pipeline v15: v14 (287.5us) + k_mlp LN-in-registers
// (no fp32 spill; smem 150KB -> 86KB -> 2 blocks/SM).

#define N_MAX 26001
#define E_MAX 520001

__device__ float   g_x[(size_t)N_MAX * 64];
__device__ __half2 g_aggh[(size_t)N_MAX * 288];   // V = half(x*agg) [N][9][32]
__device__ __half2 g_nodeh[(size_t)N_MAX * 192];  // node [N][384] as half2
__device__ float4  g_pack[(size_t)E_MAX * 3];
__device__ int     g_deg[N_MAX];
__device__ int     g_off[N_MAX + 1];
__device__ int     g_cur[N_MAX];
__device__ __half2 g_wn1h[192 * 256];             // Wn1 packed [k2][n]
__device__ __half2 g_wn2h[128 * 256];             // Wn2 packed [k2][n]
__device__ __half2 g_wuh[3 * 32 * 128];           // Wu  packed [m][k2][n]

static __device__ __forceinline__ float4 f4fma(float s, float4 w, float4 acc) {
    acc.x = fmaf(s, w.x, acc.x); acc.y = fmaf(s, w.y, acc.y);
    acc.z = fmaf(s, w.z, acc.z); acc.w = fmaf(s, w.w, acc.w);
    return acc;
}
static __device__ __forceinline__ void mma_f16(float* c, const uint32_t* a,
                                               uint32_t b0, uint32_t b1) {
    asm volatile(
        "mma.sync.aligned.m16n8k16.row.col.f32.f16.f16.f32 "
        "{%0,%1,%2,%3}, {%4,%5,%6,%7}, {%8,%9}, {%0,%1,%2,%3};"
        : "+f"(c[0]), "+f"(c[1]), "+f"(c[2]), "+f"(c[3])
        : "r"(a[0]), "r"(a[1]), "r"(a[2]), "r"(a[3]), "r"(b0), "r"(b1));
}
static __device__ __forceinline__ void cp16(void* s, const void* g) {
    uint32_t sa = (uint32_t)__cvta_generic_to_shared(s);
    asm volatile("cp.async.ca.shared.global [%0], [%1], 16;" :: "r"(sa), "l"(g));
}
#define CP_COMMIT() asm volatile("cp.async.commit_group;" ::: "memory")
#define CP_WAIT0()  asm volatile("cp.async.wait_group 0;" ::: "memory")
#define CP_WAIT1()  asm volatile("cp.async.wait_group 1;" ::: "memory")

// ---------------------------------------------------------------------------
// k_prep: pack weights to half2 [k/2][n] + zero g_deg
__global__ void k_prep(const float* __restrict__ Wn1, const float* __restrict__ Wn2,
                       const float* __restrict__ W0, const float* __restrict__ W1,
                       const float* __restrict__ Wh, int N) {
    int i = blockIdx.x * 256 + threadIdx.x;
    if (i < 49152) {
        int k2 = i >> 8, n = i & 255;
        g_wn1h[i] = __floats2half2_rn(Wn1[(size_t)(2 * k2) * 256 + n],
                                      Wn1[(size_t)(2 * k2 + 1) * 256 + n]);
    } else if (i < 81920) {
        int j = i - 49152;
        int k2 = j >> 8, n = j & 255;
        g_wn2h[j] = __floats2half2_rn(Wn2[(size_t)(2 * k2) * 256 + n],
                                      Wn2[(size_t)(2 * k2 + 1) * 256 + n]);
    } else if (i < 94208) {
        int j = i - 81920;
        int m = j >> 12;
        int r = j & 4095;
        int k2 = r >> 7, n = r & 127;
        const float* W = (m == 0) ? W0 : (m == 1) ? W1 : Wh;
        g_wuh[j] = __floats2half2_rn(W[(size_t)(2 * k2) * 128 + n],
                                     W[(size_t)(2 * k2 + 1) * 128 + n]);
    }
    if (i < N) g_deg[i] = 0;
}

// ---------------------------------------------------------------------------
__global__ void k_down(const float* __restrict__ x, const float* __restrict__ Wd,
                       const float* __restrict__ bd, int N) {
    __shared__ float sX[16 * 256];
    int t = threadIdx.x;
    int row0 = blockIdx.x * 16;
    const float4* x4 = (const float4*)x + (size_t)row0 * 64;
    int lim = (N - row0) * 64;
    for (int idx = t; idx < 1024; idx += 256)
        ((float4*)sX)[idx] = (idx < lim) ? x4[idx] : make_float4(0.f, 0.f, 0.f, 0.f);
    __syncthreads();
    int cg = t & 15, rl = t >> 4;
    int row = row0 + rl;
    if (row >= N) return;
    float4 acc = *(const float4*)(bd + cg * 4);
    const float* xr = sX + rl * 256;
#pragma unroll 8
    for (int k = 0; k < 256; k++) {
        float4 w = __ldg((const float4*)(Wd + k * 64) + cg);
        acc = f4fma(xr[k], w, acc);
    }
    *(float4*)(g_x + (size_t)row * 64 + cg * 4) = acc;
}

// ---------------------------------------------------------------------------
__global__ void k_hist(const int* __restrict__ iv, int E) {
    int e = blockIdx.x * blockDim.x + threadIdx.x;
    if (e < E) atomicAdd(&g_deg[iv[e]], 1);
}

__global__ void k_scan(int N) {
    extern __shared__ int si[];
    int* sDeg = si;
    int* sOff = si + N;
    __shared__ int warpTot[32];
    int t = threadIdx.x;
    for (int idx = t; idx < N; idx += 1024) sDeg[idx] = g_deg[idx];
    __syncthreads();
    int chunk = (N + 1023) >> 10;
    int base = t * chunk;
    int s = 0;
    for (int k = 0; k < chunk; k++) {
        int i = base + k;
        if (i < N) s += sDeg[i];
    }
    int lane = t & 31, w = t >> 5;
    int pre = s;
#pragma unroll
    for (int o = 1; o < 32; o <<= 1) {
        int u = __shfl_up_sync(0xffffffffu, pre, o);
        if (lane >= o) pre += u;
    }
    if (lane == 31) warpTot[w] = pre;
    __syncthreads();
    if (w == 0) {
        int v = warpTot[lane];
#pragma unroll
        for (int o = 1; o < 32; o <<= 1) {
            int u = __shfl_up_sync(0xffffffffu, v, o);
            if (lane >= o) v += u;
        }
        warpTot[lane] = v;
    }
    __syncthreads();
    int excl = pre - s + (w ? warpTot[w - 1] : 0);
    for (int k = 0; k < chunk; k++) {
        int i = base + k;
        if (i < N) { sOff[i] = excl; excl += sDeg[i]; }
    }
    __syncthreads();
    for (int idx = t; idx < N; idx += 1024) {
        int v = sOff[idx];
        g_off[idx] = v;
        g_cur[idx] = v;
    }
    if (t == 1023) g_off[N] = excl;
}

__global__ void k_scatter(const int* __restrict__ iv, const int* __restrict__ jv,
                          const float* __restrict__ factor,
                          const float* __restrict__ sph0, const float* __restrict__ sph1,
                          int E) {
    int e = blockIdx.x * blockDim.x + threadIdx.x;
    if (e >= E) return;
    int i = iv[e];
    int pos = atomicAdd(&g_cur[i], 1);
    float4 A, B, C;
    A.x = __int_as_float(jv[e]);
    A.y = __int_as_float(e);
    A.z = __ldg(factor + e);
    A.w = __ldg(sph1 + (size_t)e * 3 + 0);
    B.x = __ldg(sph1 + (size_t)e * 3 + 1);
    B.y = __ldg(sph1 + (size_t)e * 3 + 2);
    B.z = __ldg(sph0 + (size_t)e * 5 + 0);
    B.w = __ldg(sph0 + (size_t)e * 5 + 1);
    C.x = __ldg(sph0 + (size_t)e * 5 + 2);
    C.y = __ldg(sph0 + (size_t)e * 5 + 3);
    C.z = __ldg(sph0 + (size_t)e * 5 + 4);
    C.w = 0.f;
    g_pack[(size_t)pos * 3 + 0] = A;
    g_pack[(size_t)pos * 3 + 1] = B;
    g_pack[(size_t)pos * 3 + 2] = C;
}

// ---------------------------------------------------------------------------
// gather: warp per node; depth-2 pipeline; emits half2 V
__global__ void __launch_bounds__(256) k_gather(const float* __restrict__ rbf, int N) {
    int w = (blockIdx.x * blockDim.x + threadIdx.x) >> 5;
    if (w >= N) return;
    int lane = threadIdx.x & 31;
    float2 acc[9];
#pragma unroll
    for (int c = 0; c < 9; c++) acc[c] = make_float2(0.f, 0.f);
    int k = g_off[w], kend = g_off[w + 1];

    float4 A, B, C;
    float2 xj = make_float2(0.f, 0.f), rb = make_float2(0.f, 0.f);
    A = make_float4(0.f, 0.f, 0.f, 0.f); B = A; C = A;
    if (k < kend) {
        A = g_pack[(size_t)k * 3 + 0];
        B = g_pack[(size_t)k * 3 + 1];
        C = g_pack[(size_t)k * 3 + 2];
        int j = __float_as_int(A.x);
        int e = __float_as_int(A.y);
        xj = *(const float2*)(g_x + (size_t)j * 64 + lane * 2);
        rb = __ldg((const float2*)(rbf + (size_t)e * 64) + lane);
    }
    while (k < kend) {
        float4 An = make_float4(0.f, 0.f, 0.f, 0.f), Bn = An, Cn = An;
        float2 xjn = make_float2(0.f, 0.f), rbn = xjn;
        int kn = k + 1;
        if (kn < kend) {
            An = g_pack[(size_t)kn * 3 + 0];
            Bn = g_pack[(size_t)kn * 3 + 1];
            Cn = g_pack[(size_t)kn * 3 + 2];
            int jn = __float_as_int(An.x);
            int en = __float_as_int(An.y);
            xjn = *(const float2*)(g_x + (size_t)jn * 64 + lane * 2);
            rbn = __ldg((const float2*)(rbf + (size_t)en * 64) + lane);
        }
        float l0x = xj.x * rb.x * A.z;
        float l0y = xj.y * rb.y * A.z;
        acc[0].x += l0x;                      acc[0].y += l0y;
        acc[1].x = fmaf(A.w, l0x, acc[1].x);  acc[1].y = fmaf(A.w, l0y, acc[1].y);
        acc[2].x = fmaf(B.x, l0x, acc[2].x);  acc[2].y = fmaf(B.x, l0y, acc[2].y);
        acc[3].x = fmaf(B.y, l0x, acc[3].x);  acc[3].y = fmaf(B.y, l0y, acc[3].y);
        acc[4].x = fmaf(B.z, l0x, acc[4].x);  acc[4].y = fmaf(B.z, l0y, acc[4].y);
        acc[5].x = fmaf(B.w, l0x, acc[5].x);  acc[5].y = fmaf(B.w, l0y, acc[5].y);
        acc[6].x = fmaf(C.x, l0x, acc[6].x);  acc[6].y = fmaf(C.x, l0y, acc[6].y);
        acc[7].x = fmaf(C.y, l0x, acc[7].x);  acc[7].y = fmaf(C.y, l0y, acc[7].y);
        acc[8].x = fmaf(C.z, l0x, acc[8].x);  acc[8].y = fmaf(C.z, l0y, acc[8].y);
        A = An; B = Bn; C = Cn; xj = xjn; rb = rbn;
        k = kn;
    }
    float2 xv = *(const float2*)(g_x + (size_t)w * 64 + lane * 2);
    __half2* base = g_aggh + (size_t)w * 288 + lane;
#pragma unroll
    for (int c = 0; c < 9; c++)
        base[c * 32] = __floats2half2_rn(acc[c].x * xv.x, acc[c].y * xv.y);
}

// ---------------------------------------------------------------------------
// k_up_mma fp16: 64 nodes/block, 256 thr, 8 warps 2m x 4n, warp tile 32x32.
#define SV2 36
#define SU2 136
__global__ void __launch_bounds__(256) k_up_mma(const float* __restrict__ b0, int N) {
    extern __shared__ __half2 smh[];
    __half2* sW = smh;
    __half2* sV[2] = { smh + 4352, smh + 4352 + 2304 };
    int t = threadIdx.x, lane = t & 31, wid = t >> 5;
    int wm = wid & 1, wn = wid >> 1;
    int qr = lane >> 2, qc = lane & 3;
    int m = blockIdx.y;
    int tile0 = blockIdx.x * 64;

    int chBase = (m == 0) ? 0 : (m == 1) ? 1 : 4;
    int nch    = (m == 0) ? 1 : (m == 1) ? 3 : 5;

    {
        const __half2* Wg = g_wuh + m * 4096;
#pragma unroll
        for (int i = 0; i < 4; i++) {
            int idx = t + i * 256;
            int r = idx >> 5, c4 = (idx & 31) * 4;
            cp16(sW + r * SU2 + c4, Wg + r * 128 + c4);
        }
#pragma unroll
        for (int i = 0; i < 2; i++) {
            int idx = t + i * 256;
            int r = idx >> 3, c4 = (idx & 7) * 4;
            cp16(sV[0] + r * SV2 + c4,
                 g_aggh + (size_t)(tile0 + r) * 288 + chBase * 32 + c4);
        }
        CP_COMMIT();
    }

    float facc[2][4][4];
#pragma unroll
    for (int mt = 0; mt < 2; mt++)
#pragma unroll
        for (int nt = 0; nt < 4; nt++)
#pragma unroll
            for (int q = 0; q < 4; q++) facc[mt][nt][q] = 0.f;

    for (int ch = 0; ch < nch; ch++) {
        if (ch + 1 < nch) {
#pragma unroll
            for (int i = 0; i < 2; i++) {
                int idx = t + i * 256;
                int r = idx >> 3, c4 = (idx & 7) * 4;
                cp16(sV[(ch + 1) & 1] + r * SV2 + c4,
                     g_aggh + (size_t)(tile0 + r) * 288 + (chBase + ch + 1) * 32 + c4);
            }
            CP_COMMIT();
            CP_WAIT1();
        } else {
            CP_WAIT0();
        }
        __syncthreads();
        const __half2* V = sV[ch & 1];

        float acc[2][4][4];
#pragma unroll
        for (int mt = 0; mt < 2; mt++)
#pragma unroll
            for (int nt = 0; nt < 4; nt++)
#pragma unroll
                for (int q = 0; q < 4; q++) acc[mt][nt][q] = 0.f;

#pragma unroll
        for (int ks = 0; ks < 4; ks++) {
            int k2b = ks * 8;
            uint32_t a[2][4];
#pragma unroll
            for (int mt = 0; mt < 2; mt++) {
                const uint32_t* p = (const uint32_t*)V +
                    (wm * 32 + mt * 16 + qr) * SV2 + k2b + qc;
                a[mt][0] = p[0]; a[mt][2] = p[4];
                a[mt][1] = p[8 * SV2]; a[mt][3] = p[8 * SV2 + 4];
            }
#pragma unroll
            for (int nt = 0; nt < 4; nt++) {
                const uint32_t* pb = (const uint32_t*)sW +
                    (k2b + qc) * SU2 + wn * 32 + nt * 8 + qr;
                uint32_t b0v = pb[0], b1v = pb[4 * SU2];
                mma_f16(acc[0][nt], a[0], b0v, b1v);
                mma_f16(acc[1][nt], a[1], b0v, b1v);
            }
        }
        if (m == 0) {
#pragma unroll
            for (int mt = 0; mt < 2; mt++)
#pragma unroll
                for (int nt = 0; nt < 4; nt++)
#pragma unroll
                    for (int q = 0; q < 4; q++) facc[mt][nt][q] = acc[mt][nt][q];
        } else {
#pragma unroll
            for (int mt = 0; mt < 2; mt++)
#pragma unroll
                for (int nt = 0; nt < 4; nt++)
#pragma unroll
                    for (int q = 0; q < 4; q++)
                        facc[mt][nt][q] = fmaf(acc[mt][nt][q], acc[mt][nt][q], facc[mt][nt][q]);
        }
        __syncthreads();
    }

#pragma unroll
    for (int mt = 0; mt < 2; mt++) {
#pragma unroll
        for (int half = 0; half < 2; half++) {
            int n = tile0 + wm * 32 + mt * 16 + qr + half * 8;
            if (n < N) {
#pragma unroll
                for (int nt = 0; nt < 4; nt++) {
                    int c = wn * 32 + nt * 8 + qc * 2;
                    float ox = facc[mt][nt][half * 2 + 0];
                    float oy = facc[mt][nt][half * 2 + 1];
                    if (m == 0) { ox += __ldg(b0 + c); oy += __ldg(b0 + c + 1); }
                    g_nodeh[(size_t)n * 192 + m * 64 + wn * 16 + nt * 4 + qc] =
                        __floats2half2_rn(ox, oy);
                }
            }
        }
    }
}

// ---------------------------------------------------------------------------
// k_mlp_mma fp16 v15: 64 rows/block, 8 warps 2m x 4n, warp tile 32x64.
// LN computed in registers (shfl over qc + 4-warp smem tree); H packed
// straight into sA. smem 86KB -> 2 blocks/SM.
#define SA2 196
#define SB2 264
__global__ void __launch_bounds__(256) k_mlp_mma(
    const float* __restrict__ bn1, const float* __restrict__ lng,
    const float* __restrict__ lnb, const float* __restrict__ bn2,
    const float* __restrict__ x, float* __restrict__ out, int N) {
    extern __shared__ char smc[];
    __half2* sA = (__half2*)smc;                      // 64*196*4 = 50176 B
    float*   sR1 = (float*)(smc + 50176);             // [4][64]
    float*   sR2 = sR1 + 256;                         // [4][64]
    __half2* sWb[2] = { (__half2*)(smc + 52224),
                        (__half2*)(smc + 52224 + 16896) };
    int t = threadIdx.x, lane = t & 31, wid = t >> 5;
    int wm = wid & 1, wn = wid >> 1;
    int row0 = blockIdx.x * 64;
    int qr = lane >> 2, qc = lane & 3;

    {
#pragma unroll
        for (int i = 0; i < 12; i++) {
            int idx = t + i * 256;
            int r = idx / 48, c4 = (idx - r * 48) * 4;
            cp16(sA + r * SA2 + c4, g_nodeh + (size_t)(row0 + r) * 192 + c4);
        }
#pragma unroll
        for (int i = 0; i < 4; i++) {
            int idx = t + i * 256;
            int r = idx >> 6, c4 = (idx & 63) * 4;
            cp16(sWb[0] + r * SB2 + c4, g_wn1h + (size_t)r * 256 + c4);
        }
        CP_COMMIT();
    }

    float acc[2][8][4];
#pragma unroll
    for (int mt = 0; mt < 2; mt++)
#pragma unroll
        for (int nt = 0; nt < 8; nt++)
#pragma unroll
            for (int q = 0; q < 4; q++) acc[mt][nt][q] = 0.f;

    // GEMM1: 12 chunks of k=32
    for (int kc = 0; kc < 12; kc++) {
        if (kc + 1 < 12) {
#pragma unroll
            for (int i = 0; i < 4; i++) {
                int idx = t + i * 256;
                int r = idx >> 6, c4 = (idx & 63) * 4;
                cp16(sWb[(kc + 1) & 1] + r * SB2 + c4,
                     g_wn1h + (size_t)((kc + 1) * 16 + r) * 256 + c4);
            }
            CP_COMMIT();
            CP_WAIT1();
        } else {
            CP_WAIT0();
        }
        __syncthreads();
        const __half2* sW = sWb[kc & 1];
#pragma unroll
        for (int ks = 0; ks < 2; ks++) {
            int k2b = kc * 16 + ks * 8;
            uint32_t a[2][4];
#pragma unroll
            for (int mt = 0; mt < 2; mt++) {
                const uint32_t* p = (const uint32_t*)sA +
                    (wm * 32 + mt * 16 + qr) * SA2 + k2b + qc;
                a[mt][0] = p[0]; a[mt][2] = p[4];
                a[mt][1] = p[8 * SA2]; a[mt][3] = p[8 * SA2 + 4];
            }
#pragma unroll
            for (int nt = 0; nt < 8; nt++) {
                const uint32_t* pb = (const uint32_t*)sW +
                    (ks * 8 + qc) * SB2 + wn * 64 + nt * 8 + qr;
                uint32_t b0 = pb[0], b1 = pb[4 * SB2];
                mma_f16(acc[0][nt], a[0], b0, b1);
                mma_f16(acc[1][nt], a[1], b0, b1);
            }
        }
        __syncthreads();
    }

    // ---- LN in registers ----
    // bias add
    {
#pragma unroll
        for (int nt = 0; nt < 8; nt++) {
            int c = wn * 64 + nt * 8 + qc * 2;
            float b0v = __ldg(bn1 + c), b1v = __ldg(bn1 + c + 1);
#pragma unroll
            for (int mt = 0; mt < 2; mt++) {
                acc[mt][nt][0] += b0v; acc[mt][nt][1] += b1v;
                acc[mt][nt][2] += b0v; acc[mt][nt][3] += b1v;
            }
        }
    }
    // per-(mt,half) row partial stats, reduce over qc lanes, deposit per warp
#pragma unroll
    for (int mt = 0; mt < 2; mt++) {
#pragma unroll
        for (int half = 0; half < 2; half++) {
            float s1 = 0.f, s2 = 0.f;
#pragma unroll
            for (int nt = 0; nt < 8; nt++) {
                float a = acc[mt][nt][half * 2 + 0];
                float b = acc[mt][nt][half * 2 + 1];
                s1 += a + b;
                s2 = fmaf(a, a, fmaf(b, b, s2));
            }
            s1 += __shfl_xor_sync(0xffffffffu, s1, 1);
            s1 += __shfl_xor_sync(0xffffffffu, s1, 2);
            s2 += __shfl_xor_sync(0xffffffffu, s2, 1);
            s2 += __shfl_xor_sync(0xffffffffu, s2, 2);
            if (qc == 0) {
                int r = wm * 32 + mt * 16 + qr + half * 8;
                sR1[wn * 64 + r] = s1;
                sR2[wn * 64 + r] = s2;
            }
        }
    }
    __syncthreads();
    // apply LN + SiLU in registers, pack half2 into sA (GEMM1 done with sA)
#pragma unroll
    for (int mt = 0; mt < 2; mt++) {
#pragma unroll
        for (int half = 0; half < 2; half++) {
            int r = wm * 32 + mt * 16 + qr + half * 8;
            float fs = sR1[r] + sR1[64 + r] + sR1[128 + r] + sR1[192 + r];
            float fq = sR2[r] + sR2[64 + r] + sR2[128 + r] + sR2[192 + r];
            float mean = fs * (1.f / 256.f);
            float var = fq * (1.f / 256.f) - mean * mean;
            float rstd = rsqrtf(var + 1e-5f);
#pragma unroll
            for (int nt = 0; nt < 8; nt++) {
                int c = wn * 64 + nt * 8 + qc * 2;
                float ga = __ldg(lng + c), gb = __ldg(lng + c + 1);
                float ba = __ldg(lnb + c), bb = __ldg(lnb + c + 1);
                float ya = (acc[mt][nt][half * 2 + 0] - mean) * rstd * ga + ba;
                float yb = (acc[mt][nt][half * 2 + 1] - mean) * rstd * gb + bb;
                ya = ya / (1.f + __expf(-ya));
                yb = yb / (1.f + __expf(-yb));
                sA[r * SA2 + wn * 32 + nt * 4 + qc] = __floats2half2_rn(ya, yb);
            }
        }
    }
    // preload W2 chunk 0
    {
#pragma unroll
        for (int i = 0; i < 4; i++) {
            int idx = t + i * 256;
            int r = idx >> 6, c4 = (idx & 63) * 4;
            cp16(sWb[0] + r * SB2 + c4, g_wn2h + (size_t)r * 256 + c4);
        }
        CP_COMMIT();
    }
    __syncthreads();

    // GEMM2: 8 chunks of k=32
#pragma unroll
    for (int mt = 0; mt < 2; mt++)
#pragma unroll
        for (int nt = 0; nt < 8; nt++)
#pragma unroll
            for (int q = 0; q < 4; q++) acc[mt][nt][q] = 0.f;

    for (int kc = 0; kc < 8; kc++) {
        if (kc + 1 < 8) {
#pragma unroll
            for (int i = 0; i < 4; i++) {
                int idx = t + i * 256;
                int r = idx >> 6, c4 = (idx & 63) * 4;
                cp16(sWb[(kc + 1) & 1] + r * SB2 + c4,
                     g_wn2h + (size_t)((kc + 1) * 16 + r) * 256 + c4);
            }
            CP_COMMIT();
            CP_WAIT1();
        } else {
            CP_WAIT0();
        }
        __syncthreads();
        const __half2* sW = sWb[kc & 1];
#pragma unroll
        for (int ks = 0; ks < 2; ks++) {
            int k2b = kc * 16 + ks * 8;
            uint32_t a[2][4];
#pragma unroll
            for (int mt = 0; mt < 2; mt++) {
                const uint32_t* p = (const uint32_t*)sA +
                    (wm * 32 + mt * 16 + qr) * SA2 + k2b + qc;
                a[mt][0] = p[0]; a[mt][2] = p[4];
                a[mt][1] = p[8 * SA2]; a[mt][3] = p[8 * SA2 + 4];
            }
#pragma unroll
            for (int nt = 0; nt < 8; nt++) {
                const uint32_t* pb = (const uint32_t*)sW +
                    (ks * 8 + qc) * SB2 + wn * 64 + nt * 8 + qr;
                uint32_t b0 = pb[0], b1 = pb[4 * SB2];
                mma_f16(acc[0][nt], a[0], b0, b1);
                mma_f16(acc[1][nt], a[1], b0, b1);
            }
        }
        __syncthreads();
    }

    // epilogue: + bn2 + x -> out
#pragma unroll
    for (int mt = 0; mt < 2; mt++) {
        int rl = wm * 32 + mt * 16 + qr;
#pragma unroll
        for (int half = 0; half < 2; half++) {
            int rg = row0 + rl + half * 8;
            if (rg < N) {
#pragma unroll
                for (int nt = 0; nt < 8; nt++) {
                    int c = wn * 64 + nt * 8 + qc * 2;
                    float2 xv = __ldg((const float2*)(x + (size_t)rg * 256 + c));
                    float2 o;
                    o.x = acc[mt][nt][half * 2 + 0] + __ldg(bn2 + c) + xv.x;
                    o.y = acc[mt][nt][half * 2 + 1] + __ldg(bn2 + c + 1) + xv.y;
                    *(float2*)(out + (size_t)rg * 256 + c) = o;
                }
            }
        }
    }
}

// ---------------------------------------------------------------------------
extern "C" void kernel_launch(void* const* d_in, const int* in_sizes, int n_in,
                              void* d_out, int out_size) {
    const float* x      = (const float*)d_in[0];
    const float* rbf    = (const float*)d_in[1];
    const float* factor = (const float*)d_in[2];
    const float* sph0   = (const float*)d_in[3];
    const float* sph1   = (const float*)d_in[4];
    const float* Wd     = (const float*)d_in[5];
    const float* bd     = (const float*)d_in[6];
    const float* Wu0    = (const float*)d_in[7];
    const float* bu0    = (const float*)d_in[8];
    const float* Wu1    = (const float*)d_in[9];
    const float* Wuh    = (const float*)d_in[10];
    const float* Wn1    = (const float*)d_in[11];
    const float* bn1    = (const float*)d_in[12];
    const float* lng    = (const float*)d_in[13];
    const float* lnb    = (const float*)d_in[14];
    const float* Wn2    = (const float*)d_in[15];
    const float* bn2    = (const float*)d_in[16];
    const int*   jv     = (const int*)d_in[17];
    const int*   iv     = (const int*)d_in[18];
    float* out = (float*)d_out;

    int N = in_sizes[0] / 256;
    int E = in_sizes[17];

    int mlpSmem = 52224 + 2 * 16896;     // 86,016 B
    int upSmem  = (4352 + 2 * 2304) * 4; // 35,840 B

    static bool inited = false;
    static cudaStream_t sideStream;
    static cudaEvent_t evFork, evJoin;
    if (!inited) {
        cudaStreamCreateWithFlags(&sideStream, cudaStreamNonBlocking);
        cudaEventCreateWithFlags(&evFork, cudaEventDisableTiming);
        cudaEventCreateWithFlags(&evJoin, cudaEventDisableTiming);
        cudaFuncSetAttribute(k_up_mma,  cudaFuncAttributeMaxDynamicSharedMemorySize, upSmem);
        cudaFuncSetAttribute(k_scan,    cudaFuncAttributeMaxDynamicSharedMemorySize, 2 * (N_MAX + 4) * 4);
        cudaFuncSetAttribute(k_mlp_mma, cudaFuncAttributeMaxDynamicSharedMemorySize, mlpSmem);
        inited = true;
    }

    k_prep<<<368, 256>>>(Wn1, Wn2, Wu0, Wu1, Wuh, N);

    cudaEventRecord(evFork, 0);
    cudaStreamWaitEvent(sideStream, evFork, 0);

    k_hist<<<(E + 255) / 256, 256, 0, sideStream>>>(iv, E);
    k_scan<<<1, 1024, 2 * (N + 4) * 4, sideStream>>>(N);
    k_scatter<<<(E + 255) / 256, 256, 0, sideStream>>>(iv, jv, factor, sph0, sph1, E);

    k_down<<<(N + 15) / 16, 256>>>(x, Wd, bd, N);

    cudaEventRecord(evJoin, sideStream);
    cudaStreamWaitEvent(0, evJoin, 0);

    k_gather<<<(N + 7) / 8, 256>>>(rbf, N);
    dim3 upGrid((N + 63) / 64, 3);
    k_up_mma<<<upGrid, 256, upSmem>>>(bu0, N);
    k_mlp_mma<<<(N + 63) / 64, 256, mlpSmem>>>(bn1, lng, lnb, bn2, x, out, N);
}

// round 17
// speedup vs baseline: 1.2566x; 1.0429x over previous
#include <cuda_runtime.h>
#include <cuda_fp16.h>
#include <cstdint>

// SphConv3 fused pipeline v16: v15 (277.0us) + two-stream half-split of the
// gather->up->mlp chain (fills wave tails).

#define N_MAX 26001
#define E_MAX 520001

__device__ float   g_x[(size_t)N_MAX * 64];
__device__ __half2 g_aggh[(size_t)N_MAX * 288];
__device__ __half2 g_nodeh[(size_t)N_MAX * 192];
__device__ float4  g_pack[(size_t)E_MAX * 3];
__device__ int     g_deg[N_MAX];
__device__ int     g_off[N_MAX + 1];
__device__ int     g_cur[N_MAX];
__device__ __half2 g_wn1h[192 * 256];
__device__ __half2 g_wn2h[128 * 256];
__device__ __half2 g_wuh[3 * 32 * 128];

static __device__ __forceinline__ float4 f4fma(float s, float4 w, float4 acc) {
    acc.x = fmaf(s, w.x, acc.x); acc.y = fmaf(s, w.y, acc.y);
    acc.z = fmaf(s, w.z, acc.z); acc.w = fmaf(s, w.w, acc.w);
    return acc;
}
static __device__ __forceinline__ void mma_f16(float* c, const uint32_t* a,
                                               uint32_t b0, uint32_t b1) {
    asm volatile(
        "mma.sync.aligned.m16n8k16.row.col.f32.f16.f16.f32 "
        "{%0,%1,%2,%3}, {%4,%5,%6,%7}, {%8,%9}, {%0,%1,%2,%3};"
        : "+f"(c[0]), "+f"(c[1]), "+f"(c[2]), "+f"(c[3])
        : "r"(a[0]), "r"(a[1]), "r"(a[2]), "r"(a[3]), "r"(b0), "r"(b1));
}
static __device__ __forceinline__ void cp16(void* s, const void* g) {
    uint32_t sa = (uint32_t)__cvta_generic_to_shared(s);
    asm volatile("cp.async.ca.shared.global [%0], [%1], 16;" :: "r"(sa), "l"(g));
}
#define CP_COMMIT() asm volatile("cp.async.commit_group;" ::: "memory")
#define CP_WAIT0()  asm volatile("cp.async.wait_group 0;" ::: "memory")
#define CP_WAIT1()  asm volatile("cp.async.wait_group 1;" ::: "memory")

// ---------------------------------------------------------------------------
__global__ void k_prep(const float* __restrict__ Wn1, const float* __restrict__ Wn2,
                       const float* __restrict__ W0, const float* __restrict__ W1,
                       const float* __restrict__ Wh, int N) {
    int i = blockIdx.x * 256 + threadIdx.x;
    if (i < 49152) {
        int k2 = i >> 8, n = i & 255;
        g_wn1h[i] = __floats2half2_rn(Wn1[(size_t)(2 * k2) * 256 + n],
                                      Wn1[(size_t)(2 * k2 + 1) * 256 + n]);
    } else if (i < 81920) {
        int j = i - 49152;
        int k2 = j >> 8, n = j & 255;
        g_wn2h[j] = __floats2half2_rn(Wn2[(size_t)(2 * k2) * 256 + n],
                                      Wn2[(size_t)(2 * k2 + 1) * 256 + n]);
    } else if (i < 94208) {
        int j = i - 81920;
        int m = j >> 12;
        int r = j & 4095;
        int k2 = r >> 7, n = r & 127;
        const float* W = (m == 0) ? W0 : (m == 1) ? W1 : Wh;
        g_wuh[j] = __floats2half2_rn(W[(size_t)(2 * k2) * 128 + n],
                                     W[(size_t)(2 * k2 + 1) * 128 + n]);
    }
    if (i < N) g_deg[i] = 0;
}

// ---------------------------------------------------------------------------
__global__ void k_down(const float* __restrict__ x, const float* __restrict__ Wd,
                       const float* __restrict__ bd, int N) {
    __shared__ float sX[16 * 256];
    int t = threadIdx.x;
    int row0 = blockIdx.x * 16;
    const float4* x4 = (const float4*)x + (size_t)row0 * 64;
    int lim = (N - row0) * 64;
    for (int idx = t; idx < 1024; idx += 256)
        ((float4*)sX)[idx] = (idx < lim) ? x4[idx] : make_float4(0.f, 0.f, 0.f, 0.f);
    __syncthreads();
    int cg = t & 15, rl = t >> 4;
    int row = row0 + rl;
    if (row >= N) return;
    float4 acc = *(const float4*)(bd + cg * 4);
    const float* xr = sX + rl * 256;
#pragma unroll 8
    for (int k = 0; k < 256; k++) {
        float4 w = __ldg((const float4*)(Wd + k * 64) + cg);
        acc = f4fma(xr[k], w, acc);
    }
    *(float4*)(g_x + (size_t)row * 64 + cg * 4) = acc;
}

// ---------------------------------------------------------------------------
__global__ void k_hist(const int* __restrict__ iv, int E) {
    int e = blockIdx.x * blockDim.x + threadIdx.x;
    if (e < E) atomicAdd(&g_deg[iv[e]], 1);
}

__global__ void k_scan(int N) {
    extern __shared__ int si[];
    int* sDeg = si;
    int* sOff = si + N;
    __shared__ int warpTot[32];
    int t = threadIdx.x;
    for (int idx = t; idx < N; idx += 1024) sDeg[idx] = g_deg[idx];
    __syncthreads();
    int chunk = (N + 1023) >> 10;
    int base = t * chunk;
    int s = 0;
    for (int k = 0; k < chunk; k++) {
        int i = base + k;
        if (i < N) s += sDeg[i];
    }
    int lane = t & 31, w = t >> 5;
    int pre = s;
#pragma unroll
    for (int o = 1; o < 32; o <<= 1) {
        int u = __shfl_up_sync(0xffffffffu, pre, o);
        if (lane >= o) pre += u;
    }
    if (lane == 31) warpTot[w] = pre;
    __syncthreads();
    if (w == 0) {
        int v = warpTot[lane];
#pragma unroll
        for (int o = 1; o < 32; o <<= 1) {
            int u = __shfl_up_sync(0xffffffffu, v, o);
            if (lane >= o) v += u;
        }
        warpTot[lane] = v;
    }
    __syncthreads();
    int excl = pre - s + (w ? warpTot[w - 1] : 0);
    for (int k = 0; k < chunk; k++) {
        int i = base + k;
        if (i < N) { sOff[i] = excl; excl += sDeg[i]; }
    }
    __syncthreads();
    for (int idx = t; idx < N; idx += 1024) {
        int v = sOff[idx];
        g_off[idx] = v;
        g_cur[idx] = v;
    }
    if (t == 1023) g_off[N] = excl;
}

__global__ void k_scatter(const int* __restrict__ iv, const int* __restrict__ jv,
                          const float* __restrict__ factor,
                          const float* __restrict__ sph0, const float* __restrict__ sph1,
                          int E) {
    int e = blockIdx.x * blockDim.x + threadIdx.x;
    if (e >= E) return;
    int i = iv[e];
    int pos = atomicAdd(&g_cur[i], 1);
    float4 A, B, C;
    A.x = __int_as_float(jv[e]);
    A.y = __int_as_float(e);
    A.z = __ldg(factor + e);
    A.w = __ldg(sph1 + (size_t)e * 3 + 0);
    B.x = __ldg(sph1 + (size_t)e * 3 + 1);
    B.y = __ldg(sph1 + (size_t)e * 3 + 2);
    B.z = __ldg(sph0 + (size_t)e * 5 + 0);
    B.w = __ldg(sph0 + (size_t)e * 5 + 1);
    C.x = __ldg(sph0 + (size_t)e * 5 + 2);
    C.y = __ldg(sph0 + (size_t)e * 5 + 3);
    C.z = __ldg(sph0 + (size_t)e * 5 + 4);
    C.w = 0.f;
    g_pack[(size_t)pos * 3 + 0] = A;
    g_pack[(size_t)pos * 3 + 1] = B;
    g_pack[(size_t)pos * 3 + 2] = C;
}

// ---------------------------------------------------------------------------
// gather: warp per node in [base, Nend); depth-2 pipeline; emits half2 V
__global__ void __launch_bounds__(256) k_gather(const float* __restrict__ rbf,
                                                int base, int Nend) {
    int w = base + ((blockIdx.x * blockDim.x + threadIdx.x) >> 5);
    if (w >= Nend) return;
    int lane = threadIdx.x & 31;
    float2 acc[9];
#pragma unroll
    for (int c = 0; c < 9; c++) acc[c] = make_float2(0.f, 0.f);
    int k = g_off[w], kend = g_off[w + 1];

    float4 A, B, C;
    float2 xj = make_float2(0.f, 0.f), rb = make_float2(0.f, 0.f);
    A = make_float4(0.f, 0.f, 0.f, 0.f); B = A; C = A;
    if (k < kend) {
        A = g_pack[(size_t)k * 3 + 0];
        B = g_pack[(size_t)k * 3 + 1];
        C = g_pack[(size_t)k * 3 + 2];
        int j = __float_as_int(A.x);
        int e = __float_as_int(A.y);
        xj = *(const float2*)(g_x + (size_t)j * 64 + lane * 2);
        rb = __ldg((const float2*)(rbf + (size_t)e * 64) + lane);
    }
    while (k < kend) {
        float4 An = make_float4(0.f, 0.f, 0.f, 0.f), Bn = An, Cn = An;
        float2 xjn = make_float2(0.f, 0.f), rbn = xjn;
        int kn = k + 1;
        if (kn < kend) {
            An = g_pack[(size_t)kn * 3 + 0];
            Bn = g_pack[(size_t)kn * 3 + 1];
            Cn = g_pack[(size_t)kn * 3 + 2];
            int jn = __float_as_int(An.x);
            int en = __float_as_int(An.y);
            xjn = *(const float2*)(g_x + (size_t)jn * 64 + lane * 2);
            rbn = __ldg((const float2*)(rbf + (size_t)en * 64) + lane);
        }
        float l0x = xj.x * rb.x * A.z;
        float l0y = xj.y * rb.y * A.z;
        acc[0].x += l0x;                      acc[0].y += l0y;
        acc[1].x = fmaf(A.w, l0x, acc[1].x);  acc[1].y = fmaf(A.w, l0y, acc[1].y);
        acc[2].x = fmaf(B.x, l0x, acc[2].x);  acc[2].y = fmaf(B.x, l0y, acc[2].y);
        acc[3].x = fmaf(B.y, l0x, acc[3].x);  acc[3].y = fmaf(B.y, l0y, acc[3].y);
        acc[4].x = fmaf(B.z, l0x, acc[4].x);  acc[4].y = fmaf(B.z, l0y, acc[4].y);
        acc[5].x = fmaf(B.w, l0x, acc[5].x);  acc[5].y = fmaf(B.w, l0y, acc[5].y);
        acc[6].x = fmaf(C.x, l0x, acc[6].x);  acc[6].y = fmaf(C.x, l0y, acc[6].y);
        acc[7].x = fmaf(C.y, l0x, acc[7].x);  acc[7].y = fmaf(C.y, l0y, acc[7].y);
        acc[8].x = fmaf(C.z, l0x, acc[8].x);  acc[8].y = fmaf(C.z, l0y, acc[8].y);
        A = An; B = Bn; C = Cn; xj = xjn; rb = rbn;
        k = kn;
    }
    float2 xv = *(const float2*)(g_x + (size_t)w * 64 + lane * 2);
    __half2* base2 = g_aggh + (size_t)w * 288 + lane;
#pragma unroll
    for (int c = 0; c < 9; c++)
        base2[c * 32] = __floats2half2_rn(acc[c].x * xv.x, acc[c].y * xv.y);
}

// ---------------------------------------------------------------------------
// k_up_mma fp16: 64 nodes/block from [base, Nend).
#define SV2 36
#define SU2 136
__global__ void __launch_bounds__(256) k_up_mma(const float* __restrict__ b0,
                                                int base, int Nend) {
    extern __shared__ __half2 smh[];
    __half2* sW = smh;
    __half2* sV[2] = { smh + 4352, smh + 4352 + 2304 };
    int t = threadIdx.x, lane = t & 31, wid = t >> 5;
    int wm = wid & 1, wn = wid >> 1;
    int qr = lane >> 2, qc = lane & 3;
    int m = blockIdx.y;
    int tile0 = base + blockIdx.x * 64;

    int chBase = (m == 0) ? 0 : (m == 1) ? 1 : 4;
    int nch    = (m == 0) ? 1 : (m == 1) ? 3 : 5;

    {
        const __half2* Wg = g_wuh + m * 4096;
#pragma unroll
        for (int i = 0; i < 4; i++) {
            int idx = t + i * 256;
            int r = idx >> 5, c4 = (idx & 31) * 4;
            cp16(sW + r * SU2 + c4, Wg + r * 128 + c4);
        }
#pragma unroll
        for (int i = 0; i < 2; i++) {
            int idx = t + i * 256;
            int r = idx >> 3, c4 = (idx & 7) * 4;
            cp16(sV[0] + r * SV2 + c4,
                 g_aggh + (size_t)(tile0 + r) * 288 + chBase * 32 + c4);
        }
        CP_COMMIT();
    }

    float facc[2][4][4];
#pragma unroll
    for (int mt = 0; mt < 2; mt++)
#pragma unroll
        for (int nt = 0; nt < 4; nt++)
#pragma unroll
            for (int q = 0; q < 4; q++) facc[mt][nt][q] = 0.f;

    for (int ch = 0; ch < nch; ch++) {
        if (ch + 1 < nch) {
#pragma unroll
            for (int i = 0; i < 2; i++) {
                int idx = t + i * 256;
                int r = idx >> 3, c4 = (idx & 7) * 4;
                cp16(sV[(ch + 1) & 1] + r * SV2 + c4,
                     g_aggh + (size_t)(tile0 + r) * 288 + (chBase + ch + 1) * 32 + c4);
            }
            CP_COMMIT();
            CP_WAIT1();
        } else {
            CP_WAIT0();
        }
        __syncthreads();
        const __half2* V = sV[ch & 1];

        float acc[2][4][4];
#pragma unroll
        for (int mt = 0; mt < 2; mt++)
#pragma unroll
            for (int nt = 0; nt < 4; nt++)
#pragma unroll
                for (int q = 0; q < 4; q++) acc[mt][nt][q] = 0.f;

#pragma unroll
        for (int ks = 0; ks < 4; ks++) {
            int k2b = ks * 8;
            uint32_t a[2][4];
#pragma unroll
            for (int mt = 0; mt < 2; mt++) {
                const uint32_t* p = (const uint32_t*)V +
                    (wm * 32 + mt * 16 + qr) * SV2 + k2b + qc;
                a[mt][0] = p[0]; a[mt][2] = p[4];
                a[mt][1] = p[8 * SV2]; a[mt][3] = p[8 * SV2 + 4];
            }
#pragma unroll
            for (int nt = 0; nt < 4; nt++) {
                const uint32_t* pb = (const uint32_t*)sW +
                    (k2b + qc) * SU2 + wn * 32 + nt * 8 + qr;
                uint32_t b0v = pb[0], b1v = pb[4 * SU2];
                mma_f16(acc[0][nt], a[0], b0v, b1v);
                mma_f16(acc[1][nt], a[1], b0v, b1v);
            }
        }
        if (m == 0) {
#pragma unroll
            for (int mt = 0; mt < 2; mt++)
#pragma unroll
                for (int nt = 0; nt < 4; nt++)
#pragma unroll
                    for (int q = 0; q < 4; q++) facc[mt][nt][q] = acc[mt][nt][q];
        } else {
#pragma unroll
            for (int mt = 0; mt < 2; mt++)
#pragma unroll
                for (int nt = 0; nt < 4; nt++)
#pragma unroll
                    for (int q = 0; q < 4; q++)
                        facc[mt][nt][q] = fmaf(acc[mt][nt][q], acc[mt][nt][q], facc[mt][nt][q]);
        }
        __syncthreads();
    }

#pragma unroll
    for (int mt = 0; mt < 2; mt++) {
#pragma unroll
        for (int half = 0; half < 2; half++) {
            int n = tile0 + wm * 32 + mt * 16 + qr + half * 8;
            if (n < Nend) {
#pragma unroll
                for (int nt = 0; nt < 4; nt++) {
                    int c = wn * 32 + nt * 8 + qc * 2;
                    float ox = facc[mt][nt][half * 2 + 0];
                    float oy = facc[mt][nt][half * 2 + 1];
                    if (m == 0) { ox += __ldg(b0 + c); oy += __ldg(b0 + c + 1); }
                    g_nodeh[(size_t)n * 192 + m * 64 + wn * 16 + nt * 4 + qc] =
                        __floats2half2_rn(ox, oy);
                }
            }
        }
    }
}

// ---------------------------------------------------------------------------
// k_mlp_mma fp16: 64 rows/block from [base, Nend). LN in registers.
#define SA2 196
#define SB2 264
__global__ void __launch_bounds__(256) k_mlp_mma(
    const float* __restrict__ bn1, const float* __restrict__ lng,
    const float* __restrict__ lnb, const float* __restrict__ bn2,
    const float* __restrict__ x, float* __restrict__ out, int base, int Nend) {
    extern __shared__ char smc[];
    __half2* sA = (__half2*)smc;
    float*   sR1 = (float*)(smc + 50176);
    float*   sR2 = sR1 + 256;
    __half2* sWb[2] = { (__half2*)(smc + 52224),
                        (__half2*)(smc + 52224 + 16896) };
    int t = threadIdx.x, lane = t & 31, wid = t >> 5;
    int wm = wid & 1, wn = wid >> 1;
    int row0 = base + blockIdx.x * 64;
    int qr = lane >> 2, qc = lane & 3;

    {
#pragma unroll
        for (int i = 0; i < 12; i++) {
            int idx = t + i * 256;
            int r = idx / 48, c4 = (idx - r * 48) * 4;
            cp16(sA + r * SA2 + c4, g_nodeh + (size_t)(row0 + r) * 192 + c4);
        }
#pragma unroll
        for (int i = 0; i < 4; i++) {
            int idx = t + i * 256;
            int r = idx >> 6, c4 = (idx & 63) * 4;
            cp16(sWb[0] + r * SB2 + c4, g_wn1h + (size_t)r * 256 + c4);
        }
        CP_COMMIT();
    }

    float acc[2][8][4];
#pragma unroll
    for (int mt = 0; mt < 2; mt++)
#pragma unroll
        for (int nt = 0; nt < 8; nt++)
#pragma unroll
            for (int q = 0; q < 4; q++) acc[mt][nt][q] = 0.f;

    for (int kc = 0; kc < 12; kc++) {
        if (kc + 1 < 12) {
#pragma unroll
            for (int i = 0; i < 4; i++) {
                int idx = t + i * 256;
                int r = idx >> 6, c4 = (idx & 63) * 4;
                cp16(sWb[(kc + 1) & 1] + r * SB2 + c4,
                     g_wn1h + (size_t)((kc + 1) * 16 + r) * 256 + c4);
            }
            CP_COMMIT();
            CP_WAIT1();
        } else {
            CP_WAIT0();
        }
        __syncthreads();
        const __half2* sW = sWb[kc & 1];
#pragma unroll
        for (int ks = 0; ks < 2; ks++) {
            int k2b = kc * 16 + ks * 8;
            uint32_t a[2][4];
#pragma unroll
            for (int mt = 0; mt < 2; mt++) {
                const uint32_t* p = (const uint32_t*)sA +
                    (wm * 32 + mt * 16 + qr) * SA2 + k2b + qc;
                a[mt][0] = p[0]; a[mt][2] = p[4];
                a[mt][1] = p[8 * SA2]; a[mt][3] = p[8 * SA2 + 4];
            }
#pragma unroll
            for (int nt = 0; nt < 8; nt++) {
                const uint32_t* pb = (const uint32_t*)sW +
                    (ks * 8 + qc) * SB2 + wn * 64 + nt * 8 + qr;
                uint32_t b0 = pb[0], b1 = pb[4 * SB2];
                mma_f16(acc[0][nt], a[0], b0, b1);
                mma_f16(acc[1][nt], a[1], b0, b1);
            }
        }
        __syncthreads();
    }

    // LN in registers
    {
#pragma unroll
        for (int nt = 0; nt < 8; nt++) {
            int c = wn * 64 + nt * 8 + qc * 2;
            float b0v = __ldg(bn1 + c), b1v = __ldg(bn1 + c + 1);
#pragma unroll
            for (int mt = 0; mt < 2; mt++) {
                acc[mt][nt][0] += b0v; acc[mt][nt][1] += b1v;
                acc[mt][nt][2] += b0v; acc[mt][nt][3] += b1v;
            }
        }
    }
#pragma unroll
    for (int mt = 0; mt < 2; mt++) {
#pragma unroll
        for (int half = 0; half < 2; half++) {
            float s1 = 0.f, s2 = 0.f;
#pragma unroll
            for (int nt = 0; nt < 8; nt++) {
                float a = acc[mt][nt][half * 2 + 0];
                float b = acc[mt][nt][half * 2 + 1];
                s1 += a + b;
                s2 = fmaf(a, a, fmaf(b, b, s2));
            }
            s1 += __shfl_xor_sync(0xffffffffu, s1, 1);
            s1 += __shfl_xor_sync(0xffffffffu, s1, 2);
            s2 += __shfl_xor_sync(0xffffffffu, s2, 1);
            s2 += __shfl_xor_sync(0xffffffffu, s2, 2);
            if (qc == 0) {
                int r = wm * 32 + mt * 16 + qr + half * 8;
                sR1[wn * 64 + r] = s1;
                sR2[wn * 64 + r] = s2;
            }
        }
    }
    __syncthreads();
#pragma unroll
    for (int mt = 0; mt < 2; mt++) {
#pragma unroll
        for (int half = 0; half < 2; half++) {
            int r = wm * 32 + mt * 16 + qr + half * 8;
            float fs = sR1[r] + sR1[64 + r] + sR1[128 + r] + sR1[192 + r];
            float fq = sR2[r] + sR2[64 + r] + sR2[128 + r] + sR2[192 + r];
            float mean = fs * (1.f / 256.f);
            float var = fq * (1.f / 256.f) - mean * mean;
            float rstd = rsqrtf(var + 1e-5f);
#pragma unroll
            for (int nt = 0; nt < 8; nt++) {
                int c = wn * 64 + nt * 8 + qc * 2;
                float ga = __ldg(lng + c), gb = __ldg(lng + c + 1);
                float ba = __ldg(lnb + c), bb = __ldg(lnb + c + 1);
                float ya = (acc[mt][nt][half * 2 + 0] - mean) * rstd * ga + ba;
                float yb = (acc[mt][nt][half * 2 + 1] - mean) * rstd * gb + bb;
                ya = ya / (1.f + __expf(-ya));
                yb = yb / (1.f + __expf(-yb));
                sA[r * SA2 + wn * 32 + nt * 4 + qc] = __floats2half2_rn(ya, yb);
            }
        }
    }
    {
#pragma unroll
        for (int i = 0; i < 4; i++) {
            int idx = t + i * 256;
            int r = idx >> 6, c4 = (idx & 63) * 4;
            cp16(sWb[0] + r * SB2 + c4, g_wn2h + (size_t)r * 256 + c4);
        }
        CP_COMMIT();
    }
    __syncthreads();

#pragma unroll
    for (int mt = 0; mt < 2; mt++)
#pragma unroll
        for (int nt = 0; nt < 8; nt++)
#pragma unroll
            for (int q = 0; q < 4; q++) acc[mt][nt][q] = 0.f;

    for (int kc = 0; kc < 8; kc++) {
        if (kc + 1 < 8) {
#pragma unroll
            for (int i = 0; i < 4; i++) {
                int idx = t + i * 256;
                int r = idx >> 6, c4 = (idx & 63) * 4;
                cp16(sWb[(kc + 1) & 1] + r * SB2 + c4,
                     g_wn2h + (size_t)((kc + 1) * 16 + r) * 256 + c4);
            }
            CP_COMMIT();
            CP_WAIT1();
        } else {
            CP_WAIT0();
        }
        __syncthreads();
        const __half2* sW = sWb[kc & 1];
#pragma unroll
        for (int ks = 0; ks < 2; ks++) {
            int k2b = kc * 16 + ks * 8;
            uint32_t a[2][4];
#pragma unroll
            for (int mt = 0; mt < 2; mt++) {
                const uint32_t* p = (const uint32_t*)sA +
                    (wm * 32 + mt * 16 + qr) * SA2 + k2b + qc;
                a[mt][0] = p[0]; a[mt][2] = p[4];
                a[mt][1] = p[8 * SA2]; a[mt][3] = p[8 * SA2 + 4];
            }
#pragma unroll
            for (int nt = 0; nt < 8; nt++) {
                const uint32_t* pb = (const uint32_t*)sW +
                    (ks * 8 + qc) * SB2 + wn * 64 + nt * 8 + qr;
                uint32_t b0 = pb[0], b1 = pb[4 * SB2];
                mma_f16(acc[0][nt], a[0], b0, b1);
                mma_f16(acc[1][nt], a[1], b0, b1);
            }
        }
        __syncthreads();
    }

#pragma unroll
    for (int mt = 0; mt < 2; mt++) {
        int rl = wm * 32 + mt * 16 + qr;
#pragma unroll
        for (int half = 0; half < 2; half++) {
            int rg = row0 + rl + half * 8;
            if (rg < Nend) {
#pragma unroll
                for (int nt = 0; nt < 8; nt++) {
                    int c = wn * 64 + nt * 8 + qc * 2;
                    float2 xv = __ldg((const float2*)(x + (size_t)rg * 256 + c));
                    float2 o;
                    o.x = acc[mt][nt][half * 2 + 0] + __ldg(bn2 + c) + xv.x;
                    o.y = acc[mt][nt][half * 2 + 1] + __ldg(bn2 + c + 1) + xv.y;
                    *(float2*)(out + (size_t)rg * 256 + c) = o;
                }
            }
        }
    }
}

// ---------------------------------------------------------------------------
extern "C" void kernel_launch(void* const* d_in, const int* in_sizes, int n_in,
                              void* d_out, int out_size) {
    const float* x      = (const float*)d_in[0];
    const float* rbf    = (const float*)d_in[1];
    const float* factor = (const float*)d_in[2];
    const float* sph0   = (const float*)d_in[3];
    const float* sph1   = (const float*)d_in[4];
    const float* Wd     = (const float*)d_in[5];
    const float* bd     = (const float*)d_in[6];
    const float* Wu0    = (const float*)d_in[7];
    const float* bu0    = (const float*)d_in[8];
    const float* Wu1    = (const float*)d_in[9];
    const float* Wuh    = (const float*)d_in[10];
    const float* Wn1    = (const float*)d_in[11];
    const float* bn1    = (const float*)d_in[12];
    const float* lng    = (const float*)d_in[13];
    const float* lnb    = (const float*)d_in[14];
    const float* Wn2    = (const float*)d_in[15];
    const float* bn2    = (const float*)d_in[16];
    const int*   jv     = (const int*)d_in[17];
    const int*   iv     = (const int*)d_in[18];
    float* out = (float*)d_out;

    int N = in_sizes[0] / 256;
    int E = in_sizes[17];

    int mlpSmem = 52224 + 2 * 16896;     // 86,016 B
    int upSmem  = (4352 + 2 * 2304) * 4; // 35,840 B

    static bool inited = false;
    static cudaStream_t sideStream;
    static cudaEvent_t evFork, evJoin, evFork2, evJoin2;
    if (!inited) {
        cudaStreamCreateWithFlags(&sideStream, cudaStreamNonBlocking);
        cudaEventCreateWithFlags(&evFork,  cudaEventDisableTiming);
        cudaEventCreateWithFlags(&evJoin,  cudaEventDisableTiming);
        cudaEventCreateWithFlags(&evFork2, cudaEventDisableTiming);
        cudaEventCreateWithFlags(&evJoin2, cudaEventDisableTiming);
        cudaFuncSetAttribute(k_up_mma,  cudaFuncAttributeMaxDynamicSharedMemorySize, upSmem);
        cudaFuncSetAttribute(k_scan,    cudaFuncAttributeMaxDynamicSharedMemorySize, 2 * (N_MAX + 4) * 4);
        cudaFuncSetAttribute(k_mlp_mma, cudaFuncAttributeMaxDynamicSharedMemorySize, mlpSmem);
        inited = true;
    }

    k_prep<<<368, 256>>>(Wn1, Wn2, Wu0, Wu1, Wuh, N);

    cudaEventRecord(evFork, 0);
    cudaStreamWaitEvent(sideStream, evFork, 0);

    // side chain: CSR build
    k_hist<<<(E + 255) / 256, 256, 0, sideStream>>>(iv, E);
    k_scan<<<1, 1024, 2 * (N + 4) * 4, sideStream>>>(N);
    k_scatter<<<(E + 255) / 256, 256, 0, sideStream>>>(iv, jv, factor, sph0, sph1, E);

    // main chain: down
    k_down<<<(N + 15) / 16, 256>>>(x, Wd, bd, N);

    // join, then fork both streams at the same point
    cudaEventRecord(evJoin, sideStream);
    cudaStreamWaitEvent(0, evJoin, 0);
    cudaEventRecord(evFork2, 0);
    cudaStreamWaitEvent(sideStream, evFork2, 0);

    // half-split: [0, h) on default stream, [h, N) on side stream
    int h = ((N / 2 + 63) / 64) * 64;
    if (h > N) h = N;
    int n1 = h, n2 = N - h;

    if (n1 > 0) {
        k_gather<<<(n1 + 7) / 8, 256>>>(rbf, 0, n1);
        dim3 upG1((n1 + 63) / 64, 3);
        k_up_mma<<<upG1, 256, upSmem>>>(bu0, 0, n1);
        k_mlp_mma<<<(n1 + 63) / 64, 256, mlpSmem>>>(bn1, lng, lnb, bn2, x, out, 0, n1);
    }
    if (n2 > 0) {
        k_gather<<<(n2 + 7) / 8, 256, 0, sideStream>>>(rbf, h, N);
        dim3 upG2((n2 + 63) / 64, 3);
        k_up_mma<<<upG2, 256, upSmem, sideStream>>>(bu0, h, N);
        k_mlp_mma<<<(n2 + 63) / 64, 256, mlpSmem, sideStream>>>(bn1, lng, lnb, bn2, x, out, h, N);
    }

    cudaEventRecord(evJoin2, sideStream);
    cudaStreamWaitEvent(0, evJoin2, 0);
}